// round 9
// baseline (speedup 1.0000x reference)
#include <cuda_runtime.h>
#include <cuda_bf16.h>
#include <cstdint>

#define NN 32768
#define SWZ(o) ((o) ^ (((o) >> 3) & 0x70))

__device__ __align__(128) __nv_bfloat16 g_xh[(size_t)2 * NN * 256];
__device__ __align__(128) __nv_bfloat16 g_xl[(size_t)2 * NN * 256];
__device__ __align__(128) __nv_bfloat16 g_B1b[768u * 768];
__device__ __align__(128) float g_bias1[768];
__device__ __align__(128) __nv_bfloat16 g_swh[(size_t)2 * NN * 512];
__device__ __align__(128) __nv_bfloat16 g_swl[(size_t)2 * NN * 512];
__device__ __align__(128) float g_fx[(size_t)2 * NN * 256];
__device__ __align__(128) float g_num[2 * 8 * 64 * 32];
__device__ __align__(128) float g_den[2 * 8 * 64];
__device__ __align__(128) __nv_bfloat16 g_Mb[(size_t)2 * 256 * 1536];

__device__ __forceinline__ uint32_t s2u(const void* p) {
    uint32_t a;
    asm("{ .reg .u64 t; cvta.to.shared.u64 t, %1; cvt.u32.u64 %0, t; }" : "=r"(a) : "l"(p));
    return a;
}
__device__ __forceinline__ void cpa16(uint32_t dst, const void* src) {
    asm volatile("cp.async.cg.shared.global [%0], [%1], 16;" :: "r"(dst), "l"(src));
}
__device__ __forceinline__ void cpa_commit() { asm volatile("cp.async.commit_group;" ::: "memory"); }
template <int N>
__device__ __forceinline__ void cpa_wait() { asm volatile("cp.async.wait_group %0;" :: "n"(N) : "memory"); }

__device__ __forceinline__ void ldsm4(uint32_t* r, uint32_t addr) {
    asm volatile("ldmatrix.sync.aligned.m8n8.x4.shared.b16 {%0,%1,%2,%3}, [%4];"
                 : "=r"(r[0]), "=r"(r[1]), "=r"(r[2]), "=r"(r[3]) : "r"(addr));
}
__device__ __forceinline__ void mma_bf16(float* c, const uint32_t* a, uint32_t b0, uint32_t b1) {
    asm volatile("mma.sync.aligned.m16n8k16.row.col.f32.bf16.bf16.f32 "
                 "{%0,%1,%2,%3},{%4,%5,%6,%7},{%8,%9},{%0,%1,%2,%3};"
                 : "+f"(c[0]), "+f"(c[1]), "+f"(c[2]), "+f"(c[3])
                 : "r"(a[0]), "r"(a[1]), "r"(a[2]), "r"(a[3]), "r"(b0), "r"(b1));
}
__device__ __forceinline__ void ffma2(unsigned long long& c, unsigned long long a,
                                      unsigned long long b) {
    asm("fma.rn.f32x2 %0, %1, %2, %0;" : "+l"(c) : "l"(a), "l"(b));
}
__device__ __forceinline__ unsigned long long addf2(unsigned long long a, unsigned long long b) {
    unsigned long long o;
    asm("add.rn.f32x2 %0, %1, %2;" : "=l"(o) : "l"(a), "l"(b));
    return o;
}
__device__ __forceinline__ unsigned long long dup2(float f) {
    unsigned long long d;
    uint32_t u = __float_as_uint(f);
    asm("mov.b64 %0, {%1, %1};" : "=l"(d) : "r"(u));
    return d;
}
__device__ __forceinline__ float f2lo(unsigned long long u) { return __uint_as_float((unsigned)u); }
__device__ __forceinline__ float f2hi(unsigned long long u) { return __uint_as_float((unsigned)(u >> 32)); }

// one 64-k chunk: warp (wm 0..3, wn 0..1) computes 32x64 of the 128x128 tile
__device__ __forceinline__ void compute_chunk(uint32_t abase, uint32_t bbase, int wm, int wn,
                                              int lane, float (&acc)[2][8][4]) {
    const int l15 = lane & 15, l16 = (lane >> 4) << 4;
    uint32_t arb[2], brb[4];
    int asz[2], bsz[4];
    #pragma unroll
    for (int mf = 0; mf < 2; ++mf) {
        int r = wm * 32 + mf * 16 + l15;
        arb[mf] = abase + r * 128;
        asz[mf] = (r & 7) << 4;
    }
    #pragma unroll
    for (int ng = 0; ng < 4; ++ng) {
        int r = wn * 64 + ng * 16 + l15;
        brb[ng] = bbase + r * 128;
        bsz[ng] = (r & 7) << 4;
    }
    #pragma unroll
    for (int ks = 0; ks < 4; ++ks) {
        uint32_t a[2][4], bq[4][4];
        int cb = ks * 32 + l16;
        #pragma unroll
        for (int mf = 0; mf < 2; ++mf) ldsm4(a[mf], arb[mf] + (cb ^ asz[mf]));
        #pragma unroll
        for (int ng = 0; ng < 4; ++ng) ldsm4(bq[ng], brb[ng] + (cb ^ bsz[ng]));
        #pragma unroll
        for (int mf = 0; mf < 2; ++mf)
            #pragma unroll
            for (int nf = 0; nf < 8; ++nf)
                mma_bf16(acc[mf][nf], a[mf], bq[nf >> 1][nf & 1], bq[nf >> 1][2 + (nf & 1)]);
    }
}

// R5-style 2-stage pipelined mainloop with hoisted, compile-time staging offsets.
// Buffers: A @ sb + (c&1)*16384, B @ sb + 32768 + (c&1)*16384.
template <int NCHK, int SPLIT, int AWRAP, int ALD, int BLD>
__device__ __forceinline__ void gemm128(const __nv_bfloat16* __restrict__ Ah,
                                        const __nv_bfloat16* __restrict__ Al,
                                        const __nv_bfloat16* __restrict__ Bsrc,
                                        uint32_t sb, int wm, int wn, int lane,
                                        float (&acc)[2][8][4]) {
    const int tid = threadIdx.x;
    const uint32_t off0 = SWZ((uint32_t)((tid >> 3) * 128 + (tid & 7) * 16));
    const int sA = (tid >> 3) * ALD + (tid & 7) * 8;
    const int sB = (tid >> 3) * BLD + (tid & 7) * 8;

    auto stg = [&](int c) {
        uint32_t base = sb + (c & 1) * 16384;
        const __nv_bfloat16* pa =
            ((c < SPLIT) ? Ah + (c % AWRAP) * 64 : Al + ((c - SPLIT) % AWRAP) * 64) + sA;
        const __nv_bfloat16* pb = Bsrc + (size_t)c * 64 + sB;
        #pragma unroll
        for (int i = 0; i < 4; ++i) cpa16(base + off0 + i * 4096, pa + i * 32 * ALD);
        #pragma unroll
        for (int i = 0; i < 4; ++i)
            cpa16(base + 32768 + off0 + i * 4096, pb + i * 32 * BLD);
        cpa_commit();
    };

    stg(0);
    #pragma unroll 1
    for (int c = 0; c < NCHK; ++c) {
        if (c + 1 < NCHK) {
            stg(c + 1);
            cpa_wait<1>();
        } else {
            cpa_wait<0>();
        }
        __syncthreads();
        uint32_t ab = sb + (c & 1) * 16384;
        compute_chunk(ab, ab + 32768, wm, wn, lane, acc);
        __syncthreads();
    }
}

// ---------------- K0: folded B1 (bf16 hi/lo/hi) + bias ----------------
__global__ void k0(const float* __restrict__ Wx, const float* __restrict__ bx,
                   const float* __restrict__ Wfx, const float* __restrict__ bfx,
                   const float* __restrict__ Wsl, const float* __restrict__ bsl,
                   const float* __restrict__ temp) {
    int col = blockIdx.x, d = threadIdx.x;
    float v;
    if (col < 512) {
        int h = col >> 6, g = col & 63;
        float s = 0.f;
        #pragma unroll
        for (int c = 0; c < 32; ++c) s += Wx[(h * 32 + c) * 256 + d] * Wsl[g * 32 + c];
        float it = 1.0f / temp[h];
        v = s * it;
        if (d == 0) {
            float sb = bsl[g];
            for (int c = 0; c < 32; ++c) sb += bx[h * 32 + c] * Wsl[g * 32 + c];
            g_bias1[col] = sb * it;
        }
    } else {
        v = Wfx[(col - 512) * 256 + d];
        if (d == 0) g_bias1[col] = bfx[col - 512];
    }
    __nv_bfloat16 h16 = __float2bfloat16(v);
    __nv_bfloat16 l16 = __float2bfloat16(v - __bfloat162float(h16));
    g_B1b[(size_t)col * 768 + d] = h16;
    g_B1b[(size_t)col * 768 + 256 + d] = l16;
    g_B1b[(size_t)col * 768 + 512 + d] = h16;
}

__global__ void kprep(const float* __restrict__ x) {
    size_t i = ((size_t)blockIdx.x * 256 + threadIdx.x) * 4;
    float4 v = *(const float4*)(x + i);
    __nv_bfloat162 ha, hb, la, lb;
    ha.x = __float2bfloat16(v.x); ha.y = __float2bfloat16(v.y);
    hb.x = __float2bfloat16(v.z); hb.y = __float2bfloat16(v.w);
    la.x = __float2bfloat16(v.x - __bfloat162float(ha.x));
    la.y = __float2bfloat16(v.y - __bfloat162float(ha.y));
    lb.x = __float2bfloat16(v.z - __bfloat162float(hb.x));
    lb.y = __float2bfloat16(v.w - __bfloat162float(hb.y));
    *(uint2*)&g_xh[i] = make_uint2(*(uint32_t*)&ha, *(uint32_t*)&hb);
    *(uint2*)&g_xl[i] = make_uint2(*(uint32_t*)&la, *(uint32_t*)&lb);
}

__global__ void kzero() {
    int i = blockIdx.x * 256 + threadIdx.x;
    if (i < 2 * 8 * 64 * 32) g_num[i] = 0.f;
    int j = i - 2 * 8 * 64 * 32;
    if (j >= 0 && j < 2 * 8 * 64) g_den[j] = 0.f;
}

// ---------------- K1: [128x128] GEMM over K'=768, fused softmax / fx(fp32) ------
__global__ __launch_bounds__(256, 2) void k1() {
    extern __shared__ char sm[];
    uint32_t sb = s2u(sm);
    const int tid = threadIdx.x, lane = tid & 31, wid = tid >> 5;
    const int wm = wid & 3, wn = wid >> 2;
    const int y = blockIdx.x;  // 0..5
    const int b = blockIdx.y >> 8, t0 = (blockIdx.y & 255) * 128;
    float* bias = (float*)(sm + 65536);
    if (tid < 128) bias[tid] = g_bias1[y * 128 + tid];

    const __nv_bfloat16* xh = g_xh + (size_t)(b * NN + t0) * 256;
    const __nv_bfloat16* xl = g_xl + (size_t)(b * NN + t0) * 256;
    const __nv_bfloat16* Bsrc = g_B1b + (size_t)(y * 128) * 768;

    float acc[2][8][4];
    #pragma unroll
    for (int i = 0; i < 2; ++i)
        #pragma unroll
        for (int j = 0; j < 8; ++j)
            #pragma unroll
            for (int k = 0; k < 4; ++k) acc[i][j][k] = 0.f;

    gemm128<12, 8, 4, 256, 768>(xh, xl, Bsrc, sb, wm, wn, lane, acc);

    const int q = lane & 3, qr = lane >> 2;
    const int cbl = wn * 64;
    #pragma unroll
    for (int mf = 0; mf < 2; ++mf)
        #pragma unroll
        for (int half = 0; half < 2; ++half) {
            int rl = wm * 32 + mf * 16 + qr + half * 8;
            size_t rb = (size_t)(b * NN + t0 + rl);
            float v[8][2];
            #pragma unroll
            for (int nf = 0; nf < 8; ++nf) {
                v[nf][0] = acc[mf][nf][half * 2 + 0] + bias[cbl + nf * 8 + q * 2 + 0];
                v[nf][1] = acc[mf][nf][half * 2 + 1] + bias[cbl + nf * 8 + q * 2 + 1];
            }
            if (y < 4) {
                float m = v[0][0];
                #pragma unroll
                for (int nf = 0; nf < 8; ++nf) m = fmaxf(m, fmaxf(v[nf][0], v[nf][1]));
                m = fmaxf(m, __shfl_xor_sync(0xffffffffu, m, 1));
                m = fmaxf(m, __shfl_xor_sync(0xffffffffu, m, 2));
                float s = 0.f;
                #pragma unroll
                for (int nf = 0; nf < 8; ++nf) {
                    v[nf][0] = __expf(v[nf][0] - m);
                    v[nf][1] = __expf(v[nf][1] - m);
                    s += v[nf][0] + v[nf][1];
                }
                s += __shfl_xor_sync(0xffffffffu, s, 1);
                s += __shfl_xor_sync(0xffffffffu, s, 2);
                float inv = 1.0f / s;
                size_t base = rb * 512 + y * 128 + cbl;
                #pragma unroll
                for (int nf = 0; nf < 8; ++nf) {
                    float a = v[nf][0] * inv, bq2 = v[nf][1] * inv;
                    __nv_bfloat162 hp, lp;
                    hp.x = __float2bfloat16(a); hp.y = __float2bfloat16(bq2);
                    lp.x = __float2bfloat16(a - __bfloat162float(hp.x));
                    lp.y = __float2bfloat16(bq2 - __bfloat162float(hp.y));
                    *(uint32_t*)&g_swh[base + nf * 8 + q * 2] = *(uint32_t*)&hp;
                    *(uint32_t*)&g_swl[base + nf * 8 + q * 2] = *(uint32_t*)&lp;
                }
            } else {
                size_t base = rb * 256 + (y - 4) * 128 + cbl;
                #pragma unroll
                for (int nf = 0; nf < 8; ++nf)
                    *(float2*)&g_fx[base + nf * 8 + q * 2] = make_float2(v[nf][0], v[nf][1]);
            }
        }
}

// ---------------- K2: num = sw^T @ fx, den = colsum(sw), f32x2 packed -----------
__global__ __launch_bounds__(256) void k2() {
    __shared__ float sws[32][68];
    __shared__ float fxs[32][36];
    const int bh = blockIdx.y, b = bh >> 3, h = bh & 7;
    const int n0 = blockIdx.x * 1024;
    const int tid = threadIdx.x;
    const int q = tid & 7, o = tid >> 3;
    const int g0 = (o & 7) * 8, c0 = (o >> 3) * 8;
    unsigned long long acc2[4][8];  // [g-pair][ci]
    #pragma unroll
    for (int gp = 0; gp < 4; ++gp)
        #pragma unroll
        for (int ci = 0; ci < 8; ++ci) acc2[gp][ci] = 0ULL;
    unsigned long long dacc2[4] = {0ULL, 0ULL, 0ULL, 0ULL};
    const unsigned long long onep = dup2(1.0f);

    for (int nt = 0; nt < 1024; nt += 32) {
        __syncthreads();
        {
            int rr = tid >> 3, p = tid & 7;
            size_t nrow = (size_t)(b * NN + n0 + nt + rr);
            uint4 uh = *(const uint4*)&g_swh[nrow * 512 + h * 64 + p * 8];
            uint4 ul = *(const uint4*)&g_swl[nrow * 512 + h * 64 + p * 8];
            const __nv_bfloat162* ph = (const __nv_bfloat162*)&uh;
            const __nv_bfloat162* pl = (const __nv_bfloat162*)&ul;
            #pragma unroll
            for (int t2 = 0; t2 < 4; ++t2) {
                float2 fh = __bfloat1622float2(ph[t2]);
                float2 fl = __bfloat1622float2(pl[t2]);
                sws[rr][p * 8 + t2 * 2] = fh.x + fl.x;
                sws[rr][p * 8 + t2 * 2 + 1] = fh.y + fl.y;
            }
            *(float4*)&fxs[rr][p * 4] =
                *(const float4*)&g_fx[nrow * 256 + h * 32 + p * 4];
        }
        __syncthreads();
        #pragma unroll
        for (int i = 0; i < 4; ++i) {
            int nn = q + 8 * i;
            ulonglong2 ta = *(ulonglong2*)&sws[nn][g0];
            ulonglong2 tb = *(ulonglong2*)&sws[nn][g0 + 4];
            unsigned long long sgp[4] = {ta.x, ta.y, tb.x, tb.y};
            float fc[8];
            *(float4*)fc = *(float4*)&fxs[nn][c0];
            *(float4*)(fc + 4) = *(float4*)&fxs[nn][c0 + 4];
            unsigned long long fcd[8];
            #pragma unroll
            for (int ci = 0; ci < 8; ++ci) fcd[ci] = dup2(fc[ci]);
            if (c0 == 0)
                #pragma unroll
                for (int gp = 0; gp < 4; ++gp) ffma2(dacc2[gp], sgp[gp], onep);
            #pragma unroll
            for (int gp = 0; gp < 4; ++gp)
                #pragma unroll
                for (int ci = 0; ci < 8; ++ci) ffma2(acc2[gp][ci], sgp[gp], fcd[ci]);
        }
    }
    // packed shuffle reduction over q (lanes xor 1,2,4)
    #pragma unroll
    for (int d = 1; d < 8; d <<= 1) {
        #pragma unroll
        for (int gp = 0; gp < 4; ++gp)
            #pragma unroll
            for (int ci = 0; ci < 8; ++ci)
                acc2[gp][ci] =
                    addf2(acc2[gp][ci],
                          __shfl_xor_sync(0xffffffffu, acc2[gp][ci], d));
        if (c0 == 0)
            #pragma unroll
            for (int gp = 0; gp < 4; ++gp)
                dacc2[gp] = addf2(dacc2[gp], __shfl_xor_sync(0xffffffffu, dacc2[gp], d));
    }
    if (q == 0) {
        #pragma unroll
        for (int gp = 0; gp < 4; ++gp)
            #pragma unroll
            for (int ci = 0; ci < 8; ++ci) {
                atomicAdd(&g_num[(bh * 64 + g0 + 2 * gp) * 32 + c0 + ci], f2lo(acc2[gp][ci]));
                atomicAdd(&g_num[(bh * 64 + g0 + 2 * gp + 1) * 32 + c0 + ci], f2hi(acc2[gp][ci]));
            }
        if (c0 == 0)
            #pragma unroll
            for (int gp = 0; gp < 4; ++gp) {
                atomicAdd(&g_den[bh * 64 + g0 + 2 * gp], f2lo(dacc2[gp]));
                atomicAdd(&g_den[bh * 64 + g0 + 2 * gp + 1], f2hi(dacc2[gp]));
            }
    }
}

// ---------------- K3: slice_att -> qkv -> SDPA -> fold Wout -> g_Mb -------------
__global__ __launch_bounds__(256) void k3(const float* __restrict__ Wqkv,
                                          const float* __restrict__ Wout) {
    __shared__ float S[11264];
    float* sa = S;
    float* wq = S + 2048;
    float* qs = S + 5120;
    float* ks2 = S + 7168;
    float* vs = S + 9216;
    float* sc = S;          // overlays sa/wq after phase 2
    float* att = S + 5120;  // overlays qs after phase 4
    const int bh = blockIdx.x, b = bh >> 3, h = bh & 7;
    const int tid = threadIdx.x;
    for (int i = tid; i < 3072; i += 256) wq[i] = Wqkv[i];
    #pragma unroll
    for (int c = 0; c < 8; ++c) {
        int idx = tid * 8 + c;
        sa[idx] = g_num[bh * 2048 + idx] / (g_den[bh * 64 + (idx >> 5)] + 1e-5f);
    }
    __syncthreads();
    for (int t = tid; t < 6144; t += 256) {
        int g = t & 63, j = t >> 6;
        float s2 = 0.f;
        #pragma unroll
        for (int c = 0; c < 32; ++c) s2 += sa[g * 32 + c] * wq[j * 32 + c];
        if (j < 32) qs[g * 32 + j] = s2;
        else if (j < 64) ks2[g * 32 + (j - 32)] = s2;
        else vs[g * 32 + (j - 64)] = s2;
    }
    __syncthreads();
    for (int t = tid; t < 4096; t += 256) {
        int g = t >> 6, kk = t & 63;
        float s2 = 0.f;
        #pragma unroll
        for (int c = 0; c < 32; ++c) s2 += qs[g * 32 + c] * ks2[kk * 32 + c];
        sc[g * 65 + kk] = s2 * 0.17677669529663687f;
    }
    __syncthreads();
    if (tid < 64) {
        int g = tid;
        float m = -1e30f;
        #pragma unroll 8
        for (int kk = 0; kk < 64; ++kk) m = fmaxf(m, sc[g * 65 + kk]);
        float ssum = 0.f;
        #pragma unroll 8
        for (int kk = 0; kk < 64; ++kk) {
            float e = __expf(sc[g * 65 + kk] - m);
            sc[g * 65 + kk] = e;
            ssum += e;
        }
        float inv = 1.0f / ssum;
        #pragma unroll 8
        for (int kk = 0; kk < 64; ++kk) sc[g * 65 + kk] *= inv;
    }
    __syncthreads();
    for (int t = tid; t < 2048; t += 256) {
        int g = t >> 5, c = t & 31;
        float a = 0.f;
        #pragma unroll 8
        for (int kk = 0; kk < 64; ++kk) a += sc[g * 65 + kk] * vs[kk * 32 + c];
        att[g * 32 + c] = a;
    }
    __syncthreads();
    int d2 = tid;
    float wl[32];
    #pragma unroll
    for (int c = 0; c < 32; ++c) wl[c] = Wout[d2 * 256 + h * 32 + c];
    for (int g = 0; g < 64; ++g) {
        float s2 = 0.f;
        #pragma unroll
        for (int c = 0; c < 32; ++c) s2 += att[g * 32 + c] * wl[c];
        __nv_bfloat16 h16 = __float2bfloat16(s2);
        __nv_bfloat16 l16 = __float2bfloat16(s2 - __bfloat162float(h16));
        size_t o0 = (size_t)b * 256 * 1536 + (size_t)d2 * 1536 + h * 64 + g;
        g_Mb[o0] = h16;
        g_Mb[o0 + 512] = l16;
        g_Mb[o0 + 1024] = h16;
    }
}

// ---------------- K4: out = sw @ M + bout ([128x128] tile, K'=1536) --------------
__global__ __launch_bounds__(256, 2) void k4(float* __restrict__ out,
                                             const float* __restrict__ bout) {
    extern __shared__ char sm[];
    uint32_t sb = s2u(sm);
    const int tid = threadIdx.x, lane = tid & 31, wid = tid >> 5;
    const int wm = wid & 3, wn = wid >> 2;
    const int y = blockIdx.x;  // 0..1
    const int b = blockIdx.y >> 8, t0 = (blockIdx.y & 255) * 128;
    float* bias = (float*)(sm + 65536);
    if (tid < 128) bias[tid] = bout[y * 128 + tid];

    const __nv_bfloat16* swh = g_swh + (size_t)(b * NN + t0) * 512;
    const __nv_bfloat16* swl = g_swl + (size_t)(b * NN + t0) * 512;
    const __nv_bfloat16* Bsrc = g_Mb + (size_t)b * 256 * 1536 + (size_t)(y * 128) * 1536;

    float acc[2][8][4];
    #pragma unroll
    for (int i = 0; i < 2; ++i)
        #pragma unroll
        for (int j = 0; j < 8; ++j)
            #pragma unroll
            for (int k = 0; k < 4; ++k) acc[i][j][k] = 0.f;

    gemm128<24, 16, 8, 512, 1536>(swh, swl, Bsrc, sb, wm, wn, lane, acc);

    const int q = lane & 3, qr = lane >> 2;
    const int cbl = wn * 64;
    #pragma unroll
    for (int mf = 0; mf < 2; ++mf)
        #pragma unroll
        for (int half = 0; half < 2; ++half) {
            int rl = wm * 32 + mf * 16 + qr + half * 8;
            float* op = out + (size_t)(b * NN + t0 + rl) * 256 + y * 128 + cbl;
            #pragma unroll
            for (int nf = 0; nf < 8; ++nf) {
                float v0 = acc[mf][nf][half * 2 + 0] + bias[cbl + nf * 8 + q * 2 + 0];
                float v1 = acc[mf][nf][half * 2 + 1] + bias[cbl + nf * 8 + q * 2 + 1];
                *(float2*)(op + nf * 8 + q * 2) = make_float2(v0, v1);
            }
        }
}

extern "C" void kernel_launch(void* const* d_in, const int* in_sizes, int n_in,
                              void* d_out, int out_size) {
    const float* x = (const float*)d_in[0];
    const float* Wx = (const float*)d_in[1];
    const float* bx = (const float*)d_in[2];
    const float* Wfx = (const float*)d_in[3];
    const float* bfx = (const float*)d_in[4];
    const float* Wsl = (const float*)d_in[5];
    const float* bsl = (const float*)d_in[6];
    const float* temp = (const float*)d_in[7];
    const float* Wqkv = (const float*)d_in[8];
    const float* Wout = (const float*)d_in[9];
    const float* bout = (const float*)d_in[10];
    float* out = (float*)d_out;

    const int SMEM = 65536 + 1024;
    cudaFuncSetAttribute(k1, cudaFuncAttributeMaxDynamicSharedMemorySize, SMEM);
    cudaFuncSetAttribute(k4, cudaFuncAttributeMaxDynamicSharedMemorySize, SMEM);

    k0<<<768, 256>>>(Wx, bx, Wfx, bfx, Wsl, bsl, temp);
    kprep<<<16384, 256>>>(x);
    kzero<<<(2 * 8 * 64 * 32 + 2 * 8 * 64 + 255) / 256, 256>>>();
    k1<<<dim3(6, 512), 256, SMEM>>>();
    k2<<<dim3(32, 16), 256>>>();
    k3<<<16, 256>>>(Wqkv, Wout);
    k4<<<dim3(2, 512), 256, SMEM>>>(out, bout);
}

// round 10
// speedup vs baseline: 1.0113x; 1.0113x over previous
#include <cuda_runtime.h>
#include <cuda_bf16.h>
#include <cstdint>

#define NN 32768
#define RSTR 144          // padded smem row stride (bytes): conflict-free, no swizzle
#define TILEB (128 * RSTR)  // 18432 per tile
#define STAGEB (2 * TILEB)  // 36864 per stage (A + B)

__device__ __align__(128) __nv_bfloat16 g_xh[(size_t)2 * NN * 256];
__device__ __align__(128) __nv_bfloat16 g_xl[(size_t)2 * NN * 256];
__device__ __align__(128) __nv_bfloat16 g_B1b[768u * 768];
__device__ __align__(128) float g_bias1[768];
__device__ __align__(128) __nv_bfloat16 g_swh[(size_t)2 * NN * 512];
__device__ __align__(128) __nv_bfloat16 g_swl[(size_t)2 * NN * 512];
__device__ __align__(128) float g_fx[(size_t)2 * NN * 256];
__device__ __align__(128) float g_num[2 * 8 * 64 * 32];
__device__ __align__(128) float g_den[2 * 8 * 64];
__device__ __align__(128) __nv_bfloat16 g_Mb[(size_t)2 * 256 * 1536];

__device__ __forceinline__ uint32_t s2u(const void* p) {
    uint32_t a;
    asm("{ .reg .u64 t; cvta.to.shared.u64 t, %1; cvt.u32.u64 %0, t; }" : "=r"(a) : "l"(p));
    return a;
}
__device__ __forceinline__ void cpa16(uint32_t dst, const void* src) {
    asm volatile("cp.async.cg.shared.global [%0], [%1], 16;" :: "r"(dst), "l"(src));
}
__device__ __forceinline__ void cpa_commit() { asm volatile("cp.async.commit_group;" ::: "memory"); }
template <int N>
__device__ __forceinline__ void cpa_wait() { asm volatile("cp.async.wait_group %0;" :: "n"(N) : "memory"); }

__device__ __forceinline__ void ldsm4(uint32_t* r, uint32_t addr) {
    asm volatile("ldmatrix.sync.aligned.m8n8.x4.shared.b16 {%0,%1,%2,%3}, [%4];"
                 : "=r"(r[0]), "=r"(r[1]), "=r"(r[2]), "=r"(r[3]) : "r"(addr));
}
__device__ __forceinline__ void mma_bf16(float* c, const uint32_t* a, uint32_t b0, uint32_t b1) {
    asm volatile("mma.sync.aligned.m16n8k16.row.col.f32.bf16.bf16.f32 "
                 "{%0,%1,%2,%3},{%4,%5,%6,%7},{%8,%9},{%0,%1,%2,%3};"
                 : "+f"(c[0]), "+f"(c[1]), "+f"(c[2]), "+f"(c[3])
                 : "r"(a[0]), "r"(a[1]), "r"(a[2]), "r"(a[3]), "r"(b0), "r"(b1));
}

// one 64-k chunk: warp (wm 0..3, wn 0..1) computes 32x64 of the 128x128 tile.
// Padded layout: ldsm addresses = rowbase + ks*32 (immediate offsets, no XOR).
__device__ __forceinline__ void compute_chunk(uint32_t abase, uint32_t bbase, int wm, int wn,
                                              int lane, float (&acc)[2][8][4]) {
    const int l15 = lane & 15, l16 = (lane >> 4) << 4;
    uint32_t arb[2], brb[4];
    #pragma unroll
    for (int mf = 0; mf < 2; ++mf)
        arb[mf] = abase + (wm * 32 + mf * 16 + l15) * RSTR + l16;
    #pragma unroll
    for (int ng = 0; ng < 4; ++ng)
        brb[ng] = bbase + (wn * 64 + ng * 16 + l15) * RSTR + l16;
    #pragma unroll
    for (int ks = 0; ks < 4; ++ks) {
        uint32_t a[2][4], bq[4][4];
        #pragma unroll
        for (int mf = 0; mf < 2; ++mf) ldsm4(a[mf], arb[mf] + ks * 32);
        #pragma unroll
        for (int ng = 0; ng < 4; ++ng) ldsm4(bq[ng], brb[ng] + ks * 32);
        #pragma unroll
        for (int mf = 0; mf < 2; ++mf)
            #pragma unroll
            for (int nf = 0; nf < 8; ++nf)
                mma_bf16(acc[mf][nf], a[mf], bq[nf >> 1][nf & 1], bq[nf >> 1][2 + (nf & 1)]);
    }
}

// 2-stage pipelined mainloop, 128x128 CTA tile, chunk = 64 k, padded rows.
template <int NCHK, int SPLIT, int AWRAP, int ALD, int BLD>
__device__ __forceinline__ void gemm128(const __nv_bfloat16* __restrict__ Ah,
                                        const __nv_bfloat16* __restrict__ Al,
                                        const __nv_bfloat16* __restrict__ Bsrc,
                                        uint32_t sb, int wm, int wn, int lane,
                                        float (&acc)[2][8][4]) {
    const int tid = threadIdx.x;
    const uint32_t off0 = (uint32_t)((tid >> 3) * RSTR + (tid & 7) * 16);
    const int sA = (tid >> 3) * ALD + (tid & 7) * 8;
    const int sB = (tid >> 3) * BLD + (tid & 7) * 8;

    auto stg = [&](int c) {
        uint32_t base = sb + (c & 1) * STAGEB;
        const __nv_bfloat16* pa =
            ((c < SPLIT) ? Ah + (c % AWRAP) * 64 : Al + ((c - SPLIT) % AWRAP) * 64) + sA;
        const __nv_bfloat16* pb = Bsrc + (size_t)c * 64 + sB;
        #pragma unroll
        for (int i = 0; i < 4; ++i) cpa16(base + off0 + i * 32 * RSTR, pa + i * 32 * ALD);
        #pragma unroll
        for (int i = 0; i < 4; ++i)
            cpa16(base + TILEB + off0 + i * 32 * RSTR, pb + i * 32 * BLD);
        cpa_commit();
    };

    stg(0);
    #pragma unroll 1
    for (int c = 0; c < NCHK; ++c) {
        if (c + 1 < NCHK) {
            stg(c + 1);
            cpa_wait<1>();
        } else {
            cpa_wait<0>();
        }
        __syncthreads();
        uint32_t ab = sb + (c & 1) * STAGEB;
        compute_chunk(ab, ab + TILEB, wm, wn, lane, acc);
        __syncthreads();
    }
}

// ---------------- K0: folded B1 (bf16 hi/lo/hi) + bias ----------------
__global__ void k0(const float* __restrict__ Wx, const float* __restrict__ bx,
                   const float* __restrict__ Wfx, const float* __restrict__ bfx,
                   const float* __restrict__ Wsl, const float* __restrict__ bsl,
                   const float* __restrict__ temp) {
    int col = blockIdx.x, d = threadIdx.x;
    float v;
    if (col < 512) {
        int h = col >> 6, g = col & 63;
        float s = 0.f;
        #pragma unroll
        for (int c = 0; c < 32; ++c) s += Wx[(h * 32 + c) * 256 + d] * Wsl[g * 32 + c];
        float it = 1.0f / temp[h];
        v = s * it;
        if (d == 0) {
            float sb = bsl[g];
            for (int c = 0; c < 32; ++c) sb += bx[h * 32 + c] * Wsl[g * 32 + c];
            g_bias1[col] = sb * it;
        }
    } else {
        v = Wfx[(col - 512) * 256 + d];
        if (d == 0) g_bias1[col] = bfx[col - 512];
    }
    __nv_bfloat16 h16 = __float2bfloat16(v);
    __nv_bfloat16 l16 = __float2bfloat16(v - __bfloat162float(h16));
    g_B1b[(size_t)col * 768 + d] = h16;
    g_B1b[(size_t)col * 768 + 256 + d] = l16;
    g_B1b[(size_t)col * 768 + 512 + d] = h16;
}

__global__ void kprep(const float* __restrict__ x) {
    size_t i = ((size_t)blockIdx.x * 256 + threadIdx.x) * 4;
    float4 v = *(const float4*)(x + i);
    __nv_bfloat162 ha, hb, la, lb;
    ha.x = __float2bfloat16(v.x); ha.y = __float2bfloat16(v.y);
    hb.x = __float2bfloat16(v.z); hb.y = __float2bfloat16(v.w);
    la.x = __float2bfloat16(v.x - __bfloat162float(ha.x));
    la.y = __float2bfloat16(v.y - __bfloat162float(ha.y));
    lb.x = __float2bfloat16(v.z - __bfloat162float(hb.x));
    lb.y = __float2bfloat16(v.w - __bfloat162float(hb.y));
    *(uint2*)&g_xh[i] = make_uint2(*(uint32_t*)&ha, *(uint32_t*)&hb);
    *(uint2*)&g_xl[i] = make_uint2(*(uint32_t*)&la, *(uint32_t*)&lb);
}

__global__ void kzero() {
    int i = blockIdx.x * 256 + threadIdx.x;
    if (i < 2 * 8 * 64 * 32) g_num[i] = 0.f;
    int j = i - 2 * 8 * 64 * 32;
    if (j >= 0 && j < 2 * 8 * 64) g_den[j] = 0.f;
}

// ---------------- K1: [128x128] GEMM over K'=768, fused softmax / fx(fp32) ------
__global__ __launch_bounds__(256, 2) void k1() {
    extern __shared__ char sm[];
    uint32_t sb = s2u(sm);
    const int tid = threadIdx.x, lane = tid & 31, wid = tid >> 5;
    const int wm = wid & 3, wn = wid >> 2;
    const int y = blockIdx.x;  // 0..5
    const int b = blockIdx.y >> 8, t0 = (blockIdx.y & 255) * 128;
    float* bias = (float*)(sm + 2 * STAGEB);
    if (tid < 128) bias[tid] = g_bias1[y * 128 + tid];

    const __nv_bfloat16* xh = g_xh + (size_t)(b * NN + t0) * 256;
    const __nv_bfloat16* xl = g_xl + (size_t)(b * NN + t0) * 256;
    const __nv_bfloat16* Bsrc = g_B1b + (size_t)(y * 128) * 768;

    float acc[2][8][4];
    #pragma unroll
    for (int i = 0; i < 2; ++i)
        #pragma unroll
        for (int j = 0; j < 8; ++j)
            #pragma unroll
            for (int k = 0; k < 4; ++k) acc[i][j][k] = 0.f;

    gemm128<12, 8, 4, 256, 768>(xh, xl, Bsrc, sb, wm, wn, lane, acc);

    const int q = lane & 3, qr = lane >> 2;
    const int cbl = wn * 64;
    #pragma unroll
    for (int mf = 0; mf < 2; ++mf)
        #pragma unroll
        for (int half = 0; half < 2; ++half) {
            int rl = wm * 32 + mf * 16 + qr + half * 8;
            size_t rb = (size_t)(b * NN + t0 + rl);
            float v[8][2];
            #pragma unroll
            for (int nf = 0; nf < 8; ++nf) {
                v[nf][0] = acc[mf][nf][half * 2 + 0] + bias[cbl + nf * 8 + q * 2 + 0];
                v[nf][1] = acc[mf][nf][half * 2 + 1] + bias[cbl + nf * 8 + q * 2 + 1];
            }
            if (y < 4) {
                float m = v[0][0];
                #pragma unroll
                for (int nf = 0; nf < 8; ++nf) m = fmaxf(m, fmaxf(v[nf][0], v[nf][1]));
                m = fmaxf(m, __shfl_xor_sync(0xffffffffu, m, 1));
                m = fmaxf(m, __shfl_xor_sync(0xffffffffu, m, 2));
                float s = 0.f;
                #pragma unroll
                for (int nf = 0; nf < 8; ++nf) {
                    v[nf][0] = __expf(v[nf][0] - m);
                    v[nf][1] = __expf(v[nf][1] - m);
                    s += v[nf][0] + v[nf][1];
                }
                s += __shfl_xor_sync(0xffffffffu, s, 1);
                s += __shfl_xor_sync(0xffffffffu, s, 2);
                float inv = 1.0f / s;
                size_t base = rb * 512 + y * 128 + cbl;
                #pragma unroll
                for (int nf = 0; nf < 8; ++nf) {
                    float a = v[nf][0] * inv, bq2 = v[nf][1] * inv;
                    __nv_bfloat162 hp, lp;
                    hp.x = __float2bfloat16(a); hp.y = __float2bfloat16(bq2);
                    lp.x = __float2bfloat16(a - __bfloat162float(hp.x));
                    lp.y = __float2bfloat16(bq2 - __bfloat162float(hp.y));
                    *(uint32_t*)&g_swh[base + nf * 8 + q * 2] = *(uint32_t*)&hp;
                    *(uint32_t*)&g_swl[base + nf * 8 + q * 2] = *(uint32_t*)&lp;
                }
            } else {
                size_t base = rb * 256 + (y - 4) * 128 + cbl;
                #pragma unroll
                for (int nf = 0; nf < 8; ++nf)
                    *(float2*)&g_fx[base + nf * 8 + q * 2] = make_float2(v[nf][0], v[nf][1]);
            }
        }
}

// ---------------- K2: num = sw^T @ fx, den = colsum(sw) (plain float, R5) -------
__global__ __launch_bounds__(256) void k2() {
    __shared__ float sws[32][68];
    __shared__ float fxs[32][36];
    const int bh = blockIdx.y, b = bh >> 3, h = bh & 7;
    const int n0 = blockIdx.x * 1024;
    const int tid = threadIdx.x;
    const int q = tid & 7, o = tid >> 3;
    const int g0 = (o & 7) * 8, c0 = (o >> 3) * 8;
    float acc[8][8];
    #pragma unroll
    for (int i = 0; i < 8; ++i)
        #pragma unroll
        for (int j = 0; j < 8; ++j) acc[i][j] = 0.f;
    float dacc[8] = {0, 0, 0, 0, 0, 0, 0, 0};
    for (int nt = 0; nt < 1024; nt += 32) {
        __syncthreads();
        {
            int rr = tid >> 3, p = tid & 7;
            size_t nrow = (size_t)(b * NN + n0 + nt + rr);
            uint4 uh = *(const uint4*)&g_swh[nrow * 512 + h * 64 + p * 8];
            uint4 ul = *(const uint4*)&g_swl[nrow * 512 + h * 64 + p * 8];
            const __nv_bfloat162* ph = (const __nv_bfloat162*)&uh;
            const __nv_bfloat162* pl = (const __nv_bfloat162*)&ul;
            #pragma unroll
            for (int t2 = 0; t2 < 4; ++t2) {
                float2 fh = __bfloat1622float2(ph[t2]);
                float2 fl = __bfloat1622float2(pl[t2]);
                sws[rr][p * 8 + t2 * 2] = fh.x + fl.x;
                sws[rr][p * 8 + t2 * 2 + 1] = fh.y + fl.y;
            }
            *(float4*)&fxs[rr][p * 4] =
                *(const float4*)&g_fx[nrow * 256 + h * 32 + p * 4];
        }
        __syncthreads();
        #pragma unroll
        for (int i = 0; i < 4; ++i) {
            int nn = q + 8 * i;
            float sg[8], fc[8];
            *(float4*)sg = *(float4*)&sws[nn][g0];
            *(float4*)(sg + 4) = *(float4*)&sws[nn][g0 + 4];
            *(float4*)fc = *(float4*)&fxs[nn][c0];
            *(float4*)(fc + 4) = *(float4*)&fxs[nn][c0 + 4];
            if (c0 == 0)
                #pragma unroll
                for (int j = 0; j < 8; ++j) dacc[j] += sg[j];
            #pragma unroll
            for (int gi = 0; gi < 8; ++gi)
                #pragma unroll
                for (int ci = 0; ci < 8; ++ci) acc[gi][ci] += sg[gi] * fc[ci];
        }
    }
    #pragma unroll
    for (int d = 1; d < 8; d <<= 1)
        #pragma unroll
        for (int gi = 0; gi < 8; ++gi)
            #pragma unroll
            for (int ci = 0; ci < 8; ++ci)
                acc[gi][ci] += __shfl_xor_sync(0xffffffffu, acc[gi][ci], d);
    if (c0 == 0)
        #pragma unroll
        for (int d = 1; d < 8; d <<= 1)
            #pragma unroll
            for (int j = 0; j < 8; ++j) dacc[j] += __shfl_xor_sync(0xffffffffu, dacc[j], d);
    if (q == 0) {
        #pragma unroll
        for (int gi = 0; gi < 8; ++gi)
            #pragma unroll
            for (int ci = 0; ci < 8; ++ci)
                atomicAdd(&g_num[(bh * 64 + g0 + gi) * 32 + c0 + ci], acc[gi][ci]);
        if (c0 == 0)
            #pragma unroll
            for (int j = 0; j < 8; ++j) atomicAdd(&g_den[bh * 64 + g0 + j], dacc[j]);
    }
}

// ---------------- K3: slice_att -> qkv -> SDPA -> fold Wout -> g_Mb -------------
__global__ __launch_bounds__(256) void k3(const float* __restrict__ Wqkv,
                                          const float* __restrict__ Wout) {
    __shared__ float S[11264];
    float* sa = S;
    float* wq = S + 2048;
    float* qs = S + 5120;
    float* ks2 = S + 7168;
    float* vs = S + 9216;
    float* sc = S;          // overlays sa/wq after phase 2
    float* att = S + 5120;  // overlays qs after phase 4
    const int bh = blockIdx.x, b = bh >> 3, h = bh & 7;
    const int tid = threadIdx.x;
    for (int i = tid; i < 3072; i += 256) wq[i] = Wqkv[i];
    #pragma unroll
    for (int c = 0; c < 8; ++c) {
        int idx = tid * 8 + c;
        sa[idx] = g_num[bh * 2048 + idx] / (g_den[bh * 64 + (idx >> 5)] + 1e-5f);
    }
    __syncthreads();
    for (int t = tid; t < 6144; t += 256) {
        int g = t & 63, j = t >> 6;
        float s2 = 0.f;
        #pragma unroll
        for (int c = 0; c < 32; ++c) s2 += sa[g * 32 + c] * wq[j * 32 + c];
        if (j < 32) qs[g * 32 + j] = s2;
        else if (j < 64) ks2[g * 32 + (j - 32)] = s2;
        else vs[g * 32 + (j - 64)] = s2;
    }
    __syncthreads();
    for (int t = tid; t < 4096; t += 256) {
        int g = t >> 6, kk = t & 63;
        float s2 = 0.f;
        #pragma unroll
        for (int c = 0; c < 32; ++c) s2 += qs[g * 32 + c] * ks2[kk * 32 + c];
        sc[g * 65 + kk] = s2 * 0.17677669529663687f;
    }
    __syncthreads();
    if (tid < 64) {
        int g = tid;
        float m = -1e30f;
        #pragma unroll 8
        for (int kk = 0; kk < 64; ++kk) m = fmaxf(m, sc[g * 65 + kk]);
        float ssum = 0.f;
        #pragma unroll 8
        for (int kk = 0; kk < 64; ++kk) {
            float e = __expf(sc[g * 65 + kk] - m);
            sc[g * 65 + kk] = e;
            ssum += e;
        }
        float inv = 1.0f / ssum;
        #pragma unroll 8
        for (int kk = 0; kk < 64; ++kk) sc[g * 65 + kk] *= inv;
    }
    __syncthreads();
    for (int t = tid; t < 2048; t += 256) {
        int g = t >> 5, c = t & 31;
        float a = 0.f;
        #pragma unroll 8
        for (int kk = 0; kk < 64; ++kk) a += sc[g * 65 + kk] * vs[kk * 32 + c];
        att[g * 32 + c] = a;
    }
    __syncthreads();
    int d2 = tid;
    float wl[32];
    #pragma unroll
    for (int c = 0; c < 32; ++c) wl[c] = Wout[d2 * 256 + h * 32 + c];
    for (int g = 0; g < 64; ++g) {
        float s2 = 0.f;
        #pragma unroll
        for (int c = 0; c < 32; ++c) s2 += att[g * 32 + c] * wl[c];
        __nv_bfloat16 h16 = __float2bfloat16(s2);
        __nv_bfloat16 l16 = __float2bfloat16(s2 - __bfloat162float(h16));
        size_t o0 = (size_t)b * 256 * 1536 + (size_t)d2 * 1536 + h * 64 + g;
        g_Mb[o0] = h16;
        g_Mb[o0 + 512] = l16;
        g_Mb[o0 + 1024] = h16;
    }
}

// ---------------- K4: out = sw @ M + bout ([128x128] tile, K'=1536) --------------
__global__ __launch_bounds__(256, 2) void k4(float* __restrict__ out,
                                             const float* __restrict__ bout) {
    extern __shared__ char sm[];
    uint32_t sb = s2u(sm);
    const int tid = threadIdx.x, lane = tid & 31, wid = tid >> 5;
    const int wm = wid & 3, wn = wid >> 2;
    const int y = blockIdx.x;  // 0..1
    const int b = blockIdx.y >> 8, t0 = (blockIdx.y & 255) * 128;
    float* bias = (float*)(sm + 2 * STAGEB);
    if (tid < 128) bias[tid] = bout[y * 128 + tid];

    const __nv_bfloat16* swh = g_swh + (size_t)(b * NN + t0) * 512;
    const __nv_bfloat16* swl = g_swl + (size_t)(b * NN + t0) * 512;
    const __nv_bfloat16* Bsrc = g_Mb + (size_t)b * 256 * 1536 + (size_t)(y * 128) * 1536;

    float acc[2][8][4];
    #pragma unroll
    for (int i = 0; i < 2; ++i)
        #pragma unroll
        for (int j = 0; j < 8; ++j)
            #pragma unroll
            for (int k = 0; k < 4; ++k) acc[i][j][k] = 0.f;

    gemm128<24, 16, 8, 512, 1536>(swh, swl, Bsrc, sb, wm, wn, lane, acc);

    const int q = lane & 3, qr = lane >> 2;
    const int cbl = wn * 64;
    #pragma unroll
    for (int mf = 0; mf < 2; ++mf)
        #pragma unroll
        for (int half = 0; half < 2; ++half) {
            int rl = wm * 32 + mf * 16 + qr + half * 8;
            float* op = out + (size_t)(b * NN + t0 + rl) * 256 + y * 128 + cbl;
            #pragma unroll
            for (int nf = 0; nf < 8; ++nf) {
                float v0 = acc[mf][nf][half * 2 + 0] + bias[cbl + nf * 8 + q * 2 + 0];
                float v1 = acc[mf][nf][half * 2 + 1] + bias[cbl + nf * 8 + q * 2 + 1];
                *(float2*)(op + nf * 8 + q * 2) = make_float2(v0, v1);
            }
        }
}

extern "C" void kernel_launch(void* const* d_in, const int* in_sizes, int n_in,
                              void* d_out, int out_size) {
    const float* x = (const float*)d_in[0];
    const float* Wx = (const float*)d_in[1];
    const float* bx = (const float*)d_in[2];
    const float* Wfx = (const float*)d_in[3];
    const float* bfx = (const float*)d_in[4];
    const float* Wsl = (const float*)d_in[5];
    const float* bsl = (const float*)d_in[6];
    const float* temp = (const float*)d_in[7];
    const float* Wqkv = (const float*)d_in[8];
    const float* Wout = (const float*)d_in[9];
    const float* bout = (const float*)d_in[10];
    float* out = (float*)d_out;

    const int SMEM = 2 * STAGEB + 512;  // 74240
    cudaFuncSetAttribute(k1, cudaFuncAttributeMaxDynamicSharedMemorySize, SMEM);
    cudaFuncSetAttribute(k4, cudaFuncAttributeMaxDynamicSharedMemorySize, SMEM);

    k0<<<768, 256>>>(Wx, bx, Wfx, bfx, Wsl, bsl, temp);
    kprep<<<16384, 256>>>(x);
    kzero<<<(2 * 8 * 64 * 32 + 2 * 8 * 64 + 255) / 256, 256>>>();
    k1<<<dim3(6, 512), 256, SMEM>>>();
    k2<<<dim3(32, 16), 256>>>();
    k3<<<16, 256>>>(Wqkv, Wout);
    k4<<<dim3(2, 512), 256, SMEM>>>(out, bout);
}

// round 11
// speedup vs baseline: 1.0928x; 1.0805x over previous
#include <cuda_runtime.h>
#include <cuda_bf16.h>
#include <cstdint>

#define NN 32768
#define SWZ(o) ((o) ^ (((o) >> 3) & 0x70))

__device__ __align__(128) __nv_bfloat16 g_xh[(size_t)2 * NN * 256];
__device__ __align__(128) __nv_bfloat16 g_xl[(size_t)2 * NN * 256];
__device__ __align__(128) __nv_bfloat16 g_B1b[768u * 768];
__device__ __align__(128) float g_bias1[768];
__device__ __align__(128) __nv_bfloat16 g_swh[(size_t)2 * NN * 512];
__device__ __align__(128) __nv_bfloat16 g_swl[(size_t)2 * NN * 512];
__device__ __align__(128) float g_fx[(size_t)2 * NN * 256];
__device__ __align__(128) float g_num[2 * 8 * 64 * 32];
__device__ __align__(128) float g_den[2 * 8 * 64];
__device__ __align__(128) __nv_bfloat16 g_Mb[(size_t)2 * 256 * 1536];

__device__ __forceinline__ uint32_t s2u(const void* p) {
    uint32_t a;
    asm("{ .reg .u64 t; cvta.to.shared.u64 t, %1; cvt.u32.u64 %0, t; }" : "=r"(a) : "l"(p));
    return a;
}
__device__ __forceinline__ void cpa16(uint32_t dst, const void* src) {
    asm volatile("cp.async.cg.shared.global [%0], [%1], 16;" :: "r"(dst), "l"(src));
}
__device__ __forceinline__ void cpa_commit() { asm volatile("cp.async.commit_group;" ::: "memory"); }
template <int N>
__device__ __forceinline__ void cpa_wait() { asm volatile("cp.async.wait_group %0;" :: "n"(N) : "memory"); }

__device__ __forceinline__ void ldsm4(uint32_t* r, uint32_t addr) {
    asm volatile("ldmatrix.sync.aligned.m8n8.x4.shared.b16 {%0,%1,%2,%3}, [%4];"
                 : "=r"(r[0]), "=r"(r[1]), "=r"(r[2]), "=r"(r[3]) : "r"(addr));
}
__device__ __forceinline__ void mma_bf16(float* c, const uint32_t* a, uint32_t b0, uint32_t b1) {
    asm volatile("mma.sync.aligned.m16n8k16.row.col.f32.bf16.bf16.f32 "
                 "{%0,%1,%2,%3},{%4,%5,%6,%7},{%8,%9},{%0,%1,%2,%3};"
                 : "+f"(c[0]), "+f"(c[1]), "+f"(c[2]), "+f"(c[3])
                 : "r"(a[0]), "r"(a[1]), "r"(a[2]), "r"(a[3]), "r"(b0), "r"(b1));
}

// one 64-k chunk: warp (wm 0..3, wn 0..1) computes 32x64 of the 128x128 tile
__device__ __forceinline__ void compute_chunk(uint32_t abase, uint32_t bbase, int wm, int wn,
                                              int lane, float (&acc)[2][8][4]) {
    const int l15 = lane & 15, l16 = (lane >> 4) << 4;
    uint32_t arb[2], brb[4];
    int asz[2], bsz[4];
    #pragma unroll
    for (int mf = 0; mf < 2; ++mf) {
        int r = wm * 32 + mf * 16 + l15;
        arb[mf] = abase + r * 128;
        asz[mf] = (r & 7) << 4;
    }
    #pragma unroll
    for (int ng = 0; ng < 4; ++ng) {
        int r = wn * 64 + ng * 16 + l15;
        brb[ng] = bbase + r * 128;
        bsz[ng] = (r & 7) << 4;
    }
    #pragma unroll
    for (int ks = 0; ks < 4; ++ks) {
        uint32_t a[2][4], bq[4][4];
        int cb = ks * 32 + l16;
        #pragma unroll
        for (int mf = 0; mf < 2; ++mf) ldsm4(a[mf], arb[mf] + (cb ^ asz[mf]));
        #pragma unroll
        for (int ng = 0; ng < 4; ++ng) ldsm4(bq[ng], brb[ng] + (cb ^ bsz[ng]));
        #pragma unroll
        for (int mf = 0; mf < 2; ++mf)
            #pragma unroll
            for (int nf = 0; nf < 8; ++nf)
                mma_bf16(acc[mf][nf], a[mf], bq[nf >> 1][nf & 1], bq[nf >> 1][2 + (nf & 1)]);
    }
}

// 2-stage pipelined mainloop with hoisted, compile-time staging offsets (R9, k1=232us).
template <int NCHK, int SPLIT, int AWRAP, int ALD, int BLD>
__device__ __forceinline__ void gemm128(const __nv_bfloat16* __restrict__ Ah,
                                        const __nv_bfloat16* __restrict__ Al,
                                        const __nv_bfloat16* __restrict__ Bsrc,
                                        uint32_t sb, int wm, int wn, int lane,
                                        float (&acc)[2][8][4]) {
    const int tid = threadIdx.x;
    const uint32_t off0 = SWZ((uint32_t)((tid >> 3) * 128 + (tid & 7) * 16));
    const int sA = (tid >> 3) * ALD + (tid & 7) * 8;
    const int sB = (tid >> 3) * BLD + (tid & 7) * 8;

    auto stg = [&](int c) {
        uint32_t base = sb + (c & 1) * 16384;
        const __nv_bfloat16* pa =
            ((c < SPLIT) ? Ah + (c % AWRAP) * 64 : Al + ((c - SPLIT) % AWRAP) * 64) + sA;
        const __nv_bfloat16* pb = Bsrc + (size_t)c * 64 + sB;
        #pragma unroll
        for (int i = 0; i < 4; ++i) cpa16(base + off0 + i * 4096, pa + i * 32 * ALD);
        #pragma unroll
        for (int i = 0; i < 4; ++i)
            cpa16(base + 32768 + off0 + i * 4096, pb + i * 32 * BLD);
        cpa_commit();
    };

    stg(0);
    #pragma unroll 1
    for (int c = 0; c < NCHK; ++c) {
        if (c + 1 < NCHK) {
            stg(c + 1);
            cpa_wait<1>();
        } else {
            cpa_wait<0>();
        }
        __syncthreads();
        uint32_t ab = sb + (c & 1) * 16384;
        compute_chunk(ab, ab + 32768, wm, wn, lane, acc);
        __syncthreads();
    }
}

// ---------------- K0: folded B1 (bf16 hi/lo/hi) + bias ----------------
__global__ void k0(const float* __restrict__ Wx, const float* __restrict__ bx,
                   const float* __restrict__ Wfx, const float* __restrict__ bfx,
                   const float* __restrict__ Wsl, const float* __restrict__ bsl,
                   const float* __restrict__ temp) {
    int col = blockIdx.x, d = threadIdx.x;
    float v;
    if (col < 512) {
        int h = col >> 6, g = col & 63;
        float s = 0.f;
        #pragma unroll
        for (int c = 0; c < 32; ++c) s += Wx[(h * 32 + c) * 256 + d] * Wsl[g * 32 + c];
        float it = 1.0f / temp[h];
        v = s * it;
        if (d == 0) {
            float sb = bsl[g];
            for (int c = 0; c < 32; ++c) sb += bx[h * 32 + c] * Wsl[g * 32 + c];
            g_bias1[col] = sb * it;
        }
    } else {
        v = Wfx[(col - 512) * 256 + d];
        if (d == 0) g_bias1[col] = bfx[col - 512];
    }
    __nv_bfloat16 h16 = __float2bfloat16(v);
    __nv_bfloat16 l16 = __float2bfloat16(v - __bfloat162float(h16));
    g_B1b[(size_t)col * 768 + d] = h16;
    g_B1b[(size_t)col * 768 + 256 + d] = l16;
    g_B1b[(size_t)col * 768 + 512 + d] = h16;
}

__global__ void kprep(const float* __restrict__ x) {
    size_t i = ((size_t)blockIdx.x * 256 + threadIdx.x) * 4;
    float4 v = *(const float4*)(x + i);
    __nv_bfloat162 ha, hb, la, lb;
    ha.x = __float2bfloat16(v.x); ha.y = __float2bfloat16(v.y);
    hb.x = __float2bfloat16(v.z); hb.y = __float2bfloat16(v.w);
    la.x = __float2bfloat16(v.x - __bfloat162float(ha.x));
    la.y = __float2bfloat16(v.y - __bfloat162float(ha.y));
    lb.x = __float2bfloat16(v.z - __bfloat162float(hb.x));
    lb.y = __float2bfloat16(v.w - __bfloat162float(hb.y));
    *(uint2*)&g_xh[i] = make_uint2(*(uint32_t*)&ha, *(uint32_t*)&hb);
    *(uint2*)&g_xl[i] = make_uint2(*(uint32_t*)&la, *(uint32_t*)&lb);
}

__global__ void kzero() {
    int i = blockIdx.x * 256 + threadIdx.x;
    if (i < 2 * 8 * 64 * 32) g_num[i] = 0.f;
    int j = i - 2 * 8 * 64 * 32;
    if (j >= 0 && j < 2 * 8 * 64) g_den[j] = 0.f;
}

// ---------------- K1: [128x128] GEMM over K'=768, fused softmax / fx(fp32) ------
__global__ __launch_bounds__(256, 2) void k1() {
    extern __shared__ char sm[];
    uint32_t sb = s2u(sm);
    const int tid = threadIdx.x, lane = tid & 31, wid = tid >> 5;
    const int wm = wid & 3, wn = wid >> 2;
    const int y = blockIdx.x;  // 0..5
    const int b = blockIdx.y >> 8, t0 = (blockIdx.y & 255) * 128;
    float* bias = (float*)(sm + 65536);
    if (tid < 128) bias[tid] = g_bias1[y * 128 + tid];

    const __nv_bfloat16* xh = g_xh + (size_t)(b * NN + t0) * 256;
    const __nv_bfloat16* xl = g_xl + (size_t)(b * NN + t0) * 256;
    const __nv_bfloat16* Bsrc = g_B1b + (size_t)(y * 128) * 768;

    float acc[2][8][4];
    #pragma unroll
    for (int i = 0; i < 2; ++i)
        #pragma unroll
        for (int j = 0; j < 8; ++j)
            #pragma unroll
            for (int k = 0; k < 4; ++k) acc[i][j][k] = 0.f;

    gemm128<12, 8, 4, 256, 768>(xh, xl, Bsrc, sb, wm, wn, lane, acc);

    const int q = lane & 3, qr = lane >> 2;
    const int cbl = wn * 64;
    #pragma unroll
    for (int mf = 0; mf < 2; ++mf)
        #pragma unroll
        for (int half = 0; half < 2; ++half) {
            int rl = wm * 32 + mf * 16 + qr + half * 8;
            size_t rb = (size_t)(b * NN + t0 + rl);
            float v[8][2];
            #pragma unroll
            for (int nf = 0; nf < 8; ++nf) {
                v[nf][0] = acc[mf][nf][half * 2 + 0] + bias[cbl + nf * 8 + q * 2 + 0];
                v[nf][1] = acc[mf][nf][half * 2 + 1] + bias[cbl + nf * 8 + q * 2 + 1];
            }
            if (y < 4) {
                float m = v[0][0];
                #pragma unroll
                for (int nf = 0; nf < 8; ++nf) m = fmaxf(m, fmaxf(v[nf][0], v[nf][1]));
                m = fmaxf(m, __shfl_xor_sync(0xffffffffu, m, 1));
                m = fmaxf(m, __shfl_xor_sync(0xffffffffu, m, 2));
                float s = 0.f;
                #pragma unroll
                for (int nf = 0; nf < 8; ++nf) {
                    v[nf][0] = __expf(v[nf][0] - m);
                    v[nf][1] = __expf(v[nf][1] - m);
                    s += v[nf][0] + v[nf][1];
                }
                s += __shfl_xor_sync(0xffffffffu, s, 1);
                s += __shfl_xor_sync(0xffffffffu, s, 2);
                float inv = 1.0f / s;
                size_t base = rb * 512 + y * 128 + cbl;
                #pragma unroll
                for (int nf = 0; nf < 8; ++nf) {
                    float a = v[nf][0] * inv, bq2 = v[nf][1] * inv;
                    __nv_bfloat162 hp, lp;
                    hp.x = __float2bfloat16(a); hp.y = __float2bfloat16(bq2);
                    lp.x = __float2bfloat16(a - __bfloat162float(hp.x));
                    lp.y = __float2bfloat16(bq2 - __bfloat162float(hp.y));
                    *(uint32_t*)&g_swh[base + nf * 8 + q * 2] = *(uint32_t*)&hp;
                    *(uint32_t*)&g_swl[base + nf * 8 + q * 2] = *(uint32_t*)&lp;
                }
            } else {
                size_t base = rb * 256 + (y - 4) * 128 + cbl;
                #pragma unroll
                for (int nf = 0; nf < 8; ++nf)
                    *(float2*)&g_fx[base + nf * 8 + q * 2] = make_float2(v[nf][0], v[nf][1]);
            }
        }
}

// ---------------- K2: num = sw^T @ fx, den = colsum(sw); 8x8 reg tile -----------
__global__ __launch_bounds__(256) void k2() {
    __shared__ float sws[32][68];
    __shared__ float fxs[32][36];
    const int bh = blockIdx.y, b = bh >> 3, h = bh & 7;
    const int n0 = blockIdx.x * 512;
    const int tid = threadIdx.x;
    const int q = tid & 7, o = tid >> 3;
    const int g0 = (o & 7) * 8, c0 = (o >> 3) * 8;
    float acc[8][8];
    #pragma unroll
    for (int i = 0; i < 8; ++i)
        #pragma unroll
        for (int j = 0; j < 8; ++j) acc[i][j] = 0.f;
    float dacc[8] = {0, 0, 0, 0, 0, 0, 0, 0};
    for (int nt = 0; nt < 512; nt += 32) {
        __syncthreads();
        {
            int rr = tid >> 3, p = tid & 7;
            size_t nrow = (size_t)(b * NN + n0 + nt + rr);
            uint4 uh = *(const uint4*)&g_swh[nrow * 512 + h * 64 + p * 8];
            uint4 ul = *(const uint4*)&g_swl[nrow * 512 + h * 64 + p * 8];
            const __nv_bfloat162* ph = (const __nv_bfloat162*)&uh;
            const __nv_bfloat162* pl = (const __nv_bfloat162*)&ul;
            #pragma unroll
            for (int t2 = 0; t2 < 4; ++t2) {
                float2 fh = __bfloat1622float2(ph[t2]);
                float2 fl = __bfloat1622float2(pl[t2]);
                sws[rr][p * 8 + t2 * 2] = fh.x + fl.x;
                sws[rr][p * 8 + t2 * 2 + 1] = fh.y + fl.y;
            }
            *(float4*)&fxs[rr][p * 4] =
                *(const float4*)&g_fx[nrow * 256 + h * 32 + p * 4];
        }
        __syncthreads();
        #pragma unroll
        for (int i = 0; i < 4; ++i) {
            int nn = q + 8 * i;
            float sg[8], fc[8];
            *(float4*)sg = *(float4*)&sws[nn][g0];
            *(float4*)(sg + 4) = *(float4*)&sws[nn][g0 + 4];
            *(float4*)fc = *(float4*)&fxs[nn][c0];
            *(float4*)(fc + 4) = *(float4*)&fxs[nn][c0 + 4];
            if (c0 == 0)
                #pragma unroll
                for (int j = 0; j < 8; ++j) dacc[j] += sg[j];
            #pragma unroll
            for (int gi = 0; gi < 8; ++gi)
                #pragma unroll
                for (int ci = 0; ci < 8; ++ci) acc[gi][ci] += sg[gi] * fc[ci];
        }
    }
    #pragma unroll
    for (int d = 1; d < 8; d <<= 1)
        #pragma unroll
        for (int gi = 0; gi < 8; ++gi)
            #pragma unroll
            for (int ci = 0; ci < 8; ++ci)
                acc[gi][ci] += __shfl_xor_sync(0xffffffffu, acc[gi][ci], d);
    if (c0 == 0)
        #pragma unroll
        for (int d = 1; d < 8; d <<= 1)
            #pragma unroll
            for (int j = 0; j < 8; ++j) dacc[j] += __shfl_xor_sync(0xffffffffu, dacc[j], d);
    if (q == 0) {
        #pragma unroll
        for (int gi = 0; gi < 8; ++gi)
            #pragma unroll
            for (int ci = 0; ci < 8; ++ci)
                atomicAdd(&g_num[(bh * 64 + g0 + gi) * 32 + c0 + ci], acc[gi][ci]);
        if (c0 == 0)
            #pragma unroll
            for (int j = 0; j < 8; ++j) atomicAdd(&g_den[bh * 64 + g0 + j], dacc[j]);
    }
}

// ---------------- K3: slice_att -> qkv -> SDPA -> fold Wout -> g_Mb -------------
__global__ __launch_bounds__(256) void k3(const float* __restrict__ Wqkv,
                                          const float* __restrict__ Wout) {
    __shared__ float S[11264];
    float* sa = S;
    float* wq = S + 2048;
    float* qs = S + 5120;
    float* ks2 = S + 7168;
    float* vs = S + 9216;
    float* sc = S;          // overlays sa/wq after phase 2
    float* att = S + 5120;  // overlays qs after phase 4
    const int bh = blockIdx.x, b = bh >> 3, h = bh & 7;
    const int tid = threadIdx.x;
    for (int i = tid; i < 3072; i += 256) wq[i] = Wqkv[i];
    #pragma unroll
    for (int c = 0; c < 8; ++c) {
        int idx = tid * 8 + c;
        sa[idx] = g_num[bh * 2048 + idx] / (g_den[bh * 64 + (idx >> 5)] + 1e-5f);
    }
    __syncthreads();
    for (int t = tid; t < 6144; t += 256) {
        int g = t & 63, j = t >> 6;
        float s2 = 0.f;
        #pragma unroll
        for (int c = 0; c < 32; ++c) s2 += sa[g * 32 + c] * wq[j * 32 + c];
        if (j < 32) qs[g * 32 + j] = s2;
        else if (j < 64) ks2[g * 32 + (j - 32)] = s2;
        else vs[g * 32 + (j - 64)] = s2;
    }
    __syncthreads();
    for (int t = tid; t < 4096; t += 256) {
        int g = t >> 6, kk = t & 63;
        float s2 = 0.f;
        #pragma unroll
        for (int c = 0; c < 32; ++c) s2 += qs[g * 32 + c] * ks2[kk * 32 + c];
        sc[g * 65 + kk] = s2 * 0.17677669529663687f;
    }
    __syncthreads();
    if (tid < 64) {
        int g = tid;
        float m = -1e30f;
        #pragma unroll 8
        for (int kk = 0; kk < 64; ++kk) m = fmaxf(m, sc[g * 65 + kk]);
        float ssum = 0.f;
        #pragma unroll 8
        for (int kk = 0; kk < 64; ++kk) {
            float e = __expf(sc[g * 65 + kk] - m);
            sc[g * 65 + kk] = e;
            ssum += e;
        }
        float inv = 1.0f / ssum;
        #pragma unroll 8
        for (int kk = 0; kk < 64; ++kk) sc[g * 65 + kk] *= inv;
    }
    __syncthreads();
    for (int t = tid; t < 2048; t += 256) {
        int g = t >> 5, c = t & 31;
        float a = 0.f;
        #pragma unroll 8
        for (int kk = 0; kk < 64; ++kk) a += sc[g * 65 + kk] * vs[kk * 32 + c];
        att[g * 32 + c] = a;
    }
    __syncthreads();
    int d2 = tid;
    float wl[32];
    #pragma unroll
    for (int c = 0; c < 32; ++c) wl[c] = Wout[d2 * 256 + h * 32 + c];
    for (int g = 0; g < 64; ++g) {
        float s2 = 0.f;
        #pragma unroll
        for (int c = 0; c < 32; ++c) s2 += att[g * 32 + c] * wl[c];
        __nv_bfloat16 h16 = __float2bfloat16(s2);
        __nv_bfloat16 l16 = __float2bfloat16(s2 - __bfloat162float(h16));
        size_t o0 = (size_t)b * 256 * 1536 + (size_t)d2 * 1536 + h * 64 + g;
        g_Mb[o0] = h16;
        g_Mb[o0 + 512] = l16;
        g_Mb[o0 + 1024] = h16;
    }
}

// ---------------- K4: out = sw @ M + bout ([128x128] tile, K'=1536) --------------
__global__ __launch_bounds__(256, 2) void k4(float* __restrict__ out,
                                             const float* __restrict__ bout) {
    extern __shared__ char sm[];
    uint32_t sb = s2u(sm);
    const int tid = threadIdx.x, lane = tid & 31, wid = tid >> 5;
    const int wm = wid & 3, wn = wid >> 2;
    const int y = blockIdx.x;  // 0..1
    const int b = blockIdx.y >> 8, t0 = (blockIdx.y & 255) * 128;
    float* bias = (float*)(sm + 65536);
    if (tid < 128) bias[tid] = bout[y * 128 + tid];

    const __nv_bfloat16* swh = g_swh + (size_t)(b * NN + t0) * 512;
    const __nv_bfloat16* swl = g_swl + (size_t)(b * NN + t0) * 512;
    const __nv_bfloat16* Bsrc = g_Mb + (size_t)b * 256 * 1536 + (size_t)(y * 128) * 1536;

    float acc[2][8][4];
    #pragma unroll
    for (int i = 0; i < 2; ++i)
        #pragma unroll
        for (int j = 0; j < 8; ++j)
            #pragma unroll
            for (int k = 0; k < 4; ++k) acc[i][j][k] = 0.f;

    gemm128<24, 16, 8, 512, 1536>(swh, swl, Bsrc, sb, wm, wn, lane, acc);

    const int q = lane & 3, qr = lane >> 2;
    const int cbl = wn * 64;
    #pragma unroll
    for (int mf = 0; mf < 2; ++mf)
        #pragma unroll
        for (int half = 0; half < 2; ++half) {
            int rl = wm * 32 + mf * 16 + qr + half * 8;
            float* op = out + (size_t)(b * NN + t0 + rl) * 256 + y * 128 + cbl;
            #pragma unroll
            for (int nf = 0; nf < 8; ++nf) {
                float v0 = acc[mf][nf][half * 2 + 0] + bias[cbl + nf * 8 + q * 2 + 0];
                float v1 = acc[mf][nf][half * 2 + 1] + bias[cbl + nf * 8 + q * 2 + 1];
                *(float2*)(op + nf * 8 + q * 2) = make_float2(v0, v1);
            }
        }
}

extern "C" void kernel_launch(void* const* d_in, const int* in_sizes, int n_in,
                              void* d_out, int out_size) {
    const float* x = (const float*)d_in[0];
    const float* Wx = (const float*)d_in[1];
    const float* bx = (const float*)d_in[2];
    const float* Wfx = (const float*)d_in[3];
    const float* bfx = (const float*)d_in[4];
    const float* Wsl = (const float*)d_in[5];
    const float* bsl = (const float*)d_in[6];
    const float* temp = (const float*)d_in[7];
    const float* Wqkv = (const float*)d_in[8];
    const float* Wout = (const float*)d_in[9];
    const float* bout = (const float*)d_in[10];
    float* out = (float*)d_out;

    const int SMEM = 65536 + 1024;
    cudaFuncSetAttribute(k1, cudaFuncAttributeMaxDynamicSharedMemorySize, SMEM);
    cudaFuncSetAttribute(k4, cudaFuncAttributeMaxDynamicSharedMemorySize, SMEM);

    k0<<<768, 256>>>(Wx, bx, Wfx, bfx, Wsl, bsl, temp);
    kprep<<<16384, 256>>>(x);
    kzero<<<(2 * 8 * 64 * 32 + 2 * 8 * 64 + 255) / 256, 256>>>();
    k1<<<dim3(6, 512), 256, SMEM>>>();
    k2<<<dim3(64, 16), 256>>>();
    k3<<<16, 256>>>(Wqkv, Wout);
    k4<<<dim3(2, 512), 256, SMEM>>>(out, bout);
}

// round 12
// speedup vs baseline: 1.1347x; 1.0384x over previous
#include <cuda_runtime.h>
#include <cuda_bf16.h>
#include <cstdint>

#define NN 32768
#define SWZ(o) ((o) ^ (((o) >> 3) & 0x70))

__device__ __align__(128) __nv_bfloat16 g_xh[(size_t)2 * NN * 256];
__device__ __align__(128) __nv_bfloat16 g_xl[(size_t)2 * NN * 256];
__device__ __align__(128) __nv_bfloat16 g_B1b[768u * 768];
__device__ __align__(128) float g_bias1[768];
__device__ __align__(128) __nv_bfloat16 g_swh[(size_t)2 * NN * 512];
__device__ __align__(128) __nv_bfloat16 g_swl[(size_t)2 * NN * 512];
__device__ __align__(128) float g_fx[(size_t)2 * NN * 256];
__device__ __align__(128) float g_num[2 * 8 * 64 * 32];
__device__ __align__(128) float g_den[2 * 8 * 64];
__device__ __align__(128) __nv_bfloat16 g_Mb[(size_t)2 * 256 * 1536];

__device__ __forceinline__ uint32_t s2u(const void* p) {
    uint32_t a;
    asm("{ .reg .u64 t; cvta.to.shared.u64 t, %1; cvt.u32.u64 %0, t; }" : "=r"(a) : "l"(p));
    return a;
}
__device__ __forceinline__ void cpa16(uint32_t dst, const void* src) {
    asm volatile("cp.async.cg.shared.global [%0], [%1], 16;" :: "r"(dst), "l"(src));
}
__device__ __forceinline__ void cpa_commit() { asm volatile("cp.async.commit_group;" ::: "memory"); }
template <int N>
__device__ __forceinline__ void cpa_wait() { asm volatile("cp.async.wait_group %0;" :: "n"(N) : "memory"); }

__device__ __forceinline__ void ldsm4(uint32_t* r, uint32_t addr) {
    asm volatile("ldmatrix.sync.aligned.m8n8.x4.shared.b16 {%0,%1,%2,%3}, [%4];"
                 : "=r"(r[0]), "=r"(r[1]), "=r"(r[2]), "=r"(r[3]) : "r"(addr));
}
__device__ __forceinline__ void mma_bf16(float* c, const uint32_t* a, uint32_t b0, uint32_t b1) {
    asm volatile("mma.sync.aligned.m16n8k16.row.col.f32.bf16.bf16.f32 "
                 "{%0,%1,%2,%3},{%4,%5,%6,%7},{%8,%9},{%0,%1,%2,%3};"
                 : "+f"(c[0]), "+f"(c[1]), "+f"(c[2]), "+f"(c[3])
                 : "r"(a[0]), "r"(a[1]), "r"(a[2]), "r"(a[3]), "r"(b0), "r"(b1));
}

// one 64-k chunk: warp (wm 0..3, wn 0..1) computes 32x64 of the 128x128 tile
__device__ __forceinline__ void compute_chunk(uint32_t abase, uint32_t bbase, int wm, int wn,
                                              int lane, float (&acc)[2][8][4]) {
    const int l15 = lane & 15, l16 = (lane >> 4) << 4;
    uint32_t arb[2], brb[4];
    int asz[2], bsz[4];
    #pragma unroll
    for (int mf = 0; mf < 2; ++mf) {
        int r = wm * 32 + mf * 16 + l15;
        arb[mf] = abase + r * 128;
        asz[mf] = (r & 7) << 4;
    }
    #pragma unroll
    for (int ng = 0; ng < 4; ++ng) {
        int r = wn * 64 + ng * 16 + l15;
        brb[ng] = bbase + r * 128;
        bsz[ng] = (r & 7) << 4;
    }
    #pragma unroll
    for (int ks = 0; ks < 4; ++ks) {
        uint32_t a[2][4], bq[4][4];
        int cb = ks * 32 + l16;
        #pragma unroll
        for (int mf = 0; mf < 2; ++mf) ldsm4(a[mf], arb[mf] + (cb ^ asz[mf]));
        #pragma unroll
        for (int ng = 0; ng < 4; ++ng) ldsm4(bq[ng], brb[ng] + (cb ^ bsz[ng]));
        #pragma unroll
        for (int mf = 0; mf < 2; ++mf)
            #pragma unroll
            for (int nf = 0; nf < 8; ++nf)
                mma_bf16(acc[mf][nf], a[mf], bq[nf >> 1][nf & 1], bq[nf >> 1][2 + (nf & 1)]);
    }
}

// 2-stage pipelined mainloop with hoisted staging offsets (k1=232us measured).
template <int NCHK, int SPLIT, int AWRAP, int ALD, int BLD>
__device__ __forceinline__ void gemm128(const __nv_bfloat16* __restrict__ Ah,
                                        const __nv_bfloat16* __restrict__ Al,
                                        const __nv_bfloat16* __restrict__ Bsrc,
                                        uint32_t sb, int wm, int wn, int lane,
                                        float (&acc)[2][8][4]) {
    const int tid = threadIdx.x;
    const uint32_t off0 = SWZ((uint32_t)((tid >> 3) * 128 + (tid & 7) * 16));
    const int sA = (tid >> 3) * ALD + (tid & 7) * 8;
    const int sB = (tid >> 3) * BLD + (tid & 7) * 8;

    auto stg = [&](int c) {
        uint32_t base = sb + (c & 1) * 16384;
        const __nv_bfloat16* pa =
            ((c < SPLIT) ? Ah + (c % AWRAP) * 64 : Al + ((c - SPLIT) % AWRAP) * 64) + sA;
        const __nv_bfloat16* pb = Bsrc + (size_t)c * 64 + sB;
        #pragma unroll
        for (int i = 0; i < 4; ++i) cpa16(base + off0 + i * 4096, pa + i * 32 * ALD);
        #pragma unroll
        for (int i = 0; i < 4; ++i)
            cpa16(base + 32768 + off0 + i * 4096, pb + i * 32 * BLD);
        cpa_commit();
    };

    stg(0);
    #pragma unroll 1
    for (int c = 0; c < NCHK; ++c) {
        if (c + 1 < NCHK) {
            stg(c + 1);
            cpa_wait<1>();
        } else {
            cpa_wait<0>();
        }
        __syncthreads();
        uint32_t ab = sb + (c & 1) * 16384;
        compute_chunk(ab, ab + 32768, wm, wn, lane, acc);
        __syncthreads();
    }
}

// ---------------- K0: folded B1 (bf16 hi/lo/hi) + bias ----------------
__global__ void k0(const float* __restrict__ Wx, const float* __restrict__ bx,
                   const float* __restrict__ Wfx, const float* __restrict__ bfx,
                   const float* __restrict__ Wsl, const float* __restrict__ bsl,
                   const float* __restrict__ temp) {
    int col = blockIdx.x, d = threadIdx.x;
    float v;
    if (col < 512) {
        int h = col >> 6, g = col & 63;
        float s = 0.f;
        #pragma unroll
        for (int c = 0; c < 32; ++c) s += Wx[(h * 32 + c) * 256 + d] * Wsl[g * 32 + c];
        float it = 1.0f / temp[h];
        v = s * it;
        if (d == 0) {
            float sb = bsl[g];
            for (int c = 0; c < 32; ++c) sb += bx[h * 32 + c] * Wsl[g * 32 + c];
            g_bias1[col] = sb * it;
        }
    } else {
        v = Wfx[(col - 512) * 256 + d];
        if (d == 0) g_bias1[col] = bfx[col - 512];
    }
    __nv_bfloat16 h16 = __float2bfloat16(v);
    __nv_bfloat16 l16 = __float2bfloat16(v - __bfloat162float(h16));
    g_B1b[(size_t)col * 768 + d] = h16;
    g_B1b[(size_t)col * 768 + 256 + d] = l16;
    g_B1b[(size_t)col * 768 + 512 + d] = h16;
}

__global__ void kprep(const float* __restrict__ x) {
    size_t i = ((size_t)blockIdx.x * 256 + threadIdx.x) * 4;
    float4 v = *(const float4*)(x + i);
    __nv_bfloat162 ha, hb, la, lb;
    ha.x = __float2bfloat16(v.x); ha.y = __float2bfloat16(v.y);
    hb.x = __float2bfloat16(v.z); hb.y = __float2bfloat16(v.w);
    la.x = __float2bfloat16(v.x - __bfloat162float(ha.x));
    la.y = __float2bfloat16(v.y - __bfloat162float(ha.y));
    lb.x = __float2bfloat16(v.z - __bfloat162float(hb.x));
    lb.y = __float2bfloat16(v.w - __bfloat162float(hb.y));
    *(uint2*)&g_xh[i] = make_uint2(*(uint32_t*)&ha, *(uint32_t*)&hb);
    *(uint2*)&g_xl[i] = make_uint2(*(uint32_t*)&la, *(uint32_t*)&lb);
}

__global__ void kzero() {
    int i = blockIdx.x * 256 + threadIdx.x;
    if (i < 2 * 8 * 64 * 32) g_num[i] = 0.f;
    int j = i - 2 * 8 * 64 * 32;
    if (j >= 0 && j < 2 * 8 * 64) g_den[j] = 0.f;
}

// ---------------- K1: [128x128] GEMM over K'=768, fused softmax / fx(fp32) ------
__global__ __launch_bounds__(256, 2) void k1() {
    extern __shared__ char sm[];
    uint32_t sb = s2u(sm);
    const int tid = threadIdx.x, lane = tid & 31, wid = tid >> 5;
    const int wm = wid & 3, wn = wid >> 2;
    const int y = blockIdx.x;  // 0..5
    const int b = blockIdx.y >> 8, t0 = (blockIdx.y & 255) * 128;
    float* bias = (float*)(sm + 65536);
    if (tid < 128) bias[tid] = g_bias1[y * 128 + tid];

    const __nv_bfloat16* xh = g_xh + (size_t)(b * NN + t0) * 256;
    const __nv_bfloat16* xl = g_xl + (size_t)(b * NN + t0) * 256;
    const __nv_bfloat16* Bsrc = g_B1b + (size_t)(y * 128) * 768;

    float acc[2][8][4];
    #pragma unroll
    for (int i = 0; i < 2; ++i)
        #pragma unroll
        for (int j = 0; j < 8; ++j)
            #pragma unroll
            for (int k = 0; k < 4; ++k) acc[i][j][k] = 0.f;

    gemm128<12, 8, 4, 256, 768>(xh, xl, Bsrc, sb, wm, wn, lane, acc);

    const int q = lane & 3, qr = lane >> 2;
    const int cbl = wn * 64;
    #pragma unroll
    for (int mf = 0; mf < 2; ++mf)
        #pragma unroll
        for (int half = 0; half < 2; ++half) {
            int rl = wm * 32 + mf * 16 + qr + half * 8;
            size_t rb = (size_t)(b * NN + t0 + rl);
            float v[8][2];
            #pragma unroll
            for (int nf = 0; nf < 8; ++nf) {
                v[nf][0] = acc[mf][nf][half * 2 + 0] + bias[cbl + nf * 8 + q * 2 + 0];
                v[nf][1] = acc[mf][nf][half * 2 + 1] + bias[cbl + nf * 8 + q * 2 + 1];
            }
            if (y < 4) {
                float m = v[0][0];
                #pragma unroll
                for (int nf = 0; nf < 8; ++nf) m = fmaxf(m, fmaxf(v[nf][0], v[nf][1]));
                m = fmaxf(m, __shfl_xor_sync(0xffffffffu, m, 1));
                m = fmaxf(m, __shfl_xor_sync(0xffffffffu, m, 2));
                float s = 0.f;
                #pragma unroll
                for (int nf = 0; nf < 8; ++nf) {
                    v[nf][0] = __expf(v[nf][0] - m);
                    v[nf][1] = __expf(v[nf][1] - m);
                    s += v[nf][0] + v[nf][1];
                }
                s += __shfl_xor_sync(0xffffffffu, s, 1);
                s += __shfl_xor_sync(0xffffffffu, s, 2);
                float inv = 1.0f / s;
                size_t base = rb * 512 + y * 128 + cbl;
                #pragma unroll
                for (int nf = 0; nf < 8; ++nf) {
                    float a = v[nf][0] * inv, bq2 = v[nf][1] * inv;
                    __nv_bfloat162 hp, lp;
                    hp.x = __float2bfloat16(a); hp.y = __float2bfloat16(bq2);
                    lp.x = __float2bfloat16(a - __bfloat162float(hp.x));
                    lp.y = __float2bfloat16(bq2 - __bfloat162float(hp.y));
                    *(uint32_t*)&g_swh[base + nf * 8 + q * 2] = *(uint32_t*)&hp;
                    *(uint32_t*)&g_swl[base + nf * 8 + q * 2] = *(uint32_t*)&lp;
                }
            } else {
                size_t base = rb * 256 + (y - 4) * 128 + cbl;
                #pragma unroll
                for (int nf = 0; nf < 8; ++nf)
                    *(float2*)&g_fx[base + nf * 8 + q * 2] = make_float2(v[nf][0], v[nf][1]);
            }
        }
}

// ---------------- K2: num = sw^T @ fx, den = colsum(sw); 4-stage cp.async --------
// per-stage smem block (13824B): [swh 32x144B][swl 32x144B][fx 32x144B]
__global__ __launch_bounds__(256) void k2() {
    extern __shared__ char sm[];
    const uint32_t sb = s2u(sm);
    const int bh = blockIdx.y, b = bh >> 3, h = bh & 7;
    const int n0 = blockIdx.x * 1024;
    const int tid = threadIdx.x;
    const int q = tid & 7, o = tid >> 3;
    const int g0 = (o & 7) * 8, c0 = (o >> 3) * 8;
    const int rr = tid >> 3, p = tid & 7;

    const uint32_t dsh = sb + rr * 144 + p * 16;
    const uint32_t dsl = dsh + 4608;
    const uint32_t dfx = sb + 9216 + rr * 144 + p * 16;
    const __nv_bfloat16* psh = &g_swh[((size_t)(b * NN + n0 + rr)) * 512 + h * 64 + p * 8];
    const __nv_bfloat16* psl = &g_swl[((size_t)(b * NN + n0 + rr)) * 512 + h * 64 + p * 8];
    const float* pfx = &g_fx[((size_t)(b * NN + n0 + rr)) * 256 + h * 32 + p * 4];

    auto stg = [&](int s) {
        uint32_t so = (s & 3) * 13824;
        size_t ro = (size_t)s * 32;
        cpa16(dsh + so, psh + ro * 512);
        cpa16(dsl + so, psl + ro * 512);
        cpa16(dfx + so, pfx + ro * 256);
        cpa_commit();
    };

    float acc[8][8];
    #pragma unroll
    for (int i = 0; i < 8; ++i)
        #pragma unroll
        for (int j = 0; j < 8; ++j) acc[i][j] = 0.f;
    float dacc[8] = {0, 0, 0, 0, 0, 0, 0, 0};

    stg(0); stg(1); stg(2); stg(3);
    #pragma unroll 1
    for (int c = 0; c < 32; ++c) {
        cpa_wait<3>();
        __syncthreads();
        const char* st = sm + (c & 3) * 13824;
        #pragma unroll
        for (int i = 0; i < 4; ++i) {
            int nn = q + 8 * i;
            uint4 uh = *(const uint4*)(st + nn * 144 + g0 * 2);
            uint4 ul = *(const uint4*)(st + 4608 + nn * 144 + g0 * 2);
            float fc[8];
            *(float4*)fc = *(const float4*)(st + 9216 + nn * 144 + c0 * 4);
            *(float4*)(fc + 4) = *(const float4*)(st + 9216 + nn * 144 + c0 * 4 + 16);
            const __nv_bfloat162* ph = (const __nv_bfloat162*)&uh;
            const __nv_bfloat162* pl = (const __nv_bfloat162*)&ul;
            float sg[8];
            #pragma unroll
            for (int t2 = 0; t2 < 4; ++t2) {
                float2 fh = __bfloat1622float2(ph[t2]);
                float2 fl = __bfloat1622float2(pl[t2]);
                sg[t2 * 2] = fh.x + fl.x;
                sg[t2 * 2 + 1] = fh.y + fl.y;
            }
            if (c0 == 0)
                #pragma unroll
                for (int j = 0; j < 8; ++j) dacc[j] += sg[j];
            #pragma unroll
            for (int gi = 0; gi < 8; ++gi)
                #pragma unroll
                for (int ci = 0; ci < 8; ++ci) acc[gi][ci] += sg[gi] * fc[ci];
        }
        __syncthreads();
        if (c + 4 < 32) stg(c + 4); else cpa_commit();
    }

    #pragma unroll
    for (int d = 1; d < 8; d <<= 1)
        #pragma unroll
        for (int gi = 0; gi < 8; ++gi)
            #pragma unroll
            for (int ci = 0; ci < 8; ++ci)
                acc[gi][ci] += __shfl_xor_sync(0xffffffffu, acc[gi][ci], d);
    if (c0 == 0)
        #pragma unroll
        for (int d = 1; d < 8; d <<= 1)
            #pragma unroll
            for (int j = 0; j < 8; ++j) dacc[j] += __shfl_xor_sync(0xffffffffu, dacc[j], d);
    if (q == 0) {
        #pragma unroll
        for (int gi = 0; gi < 8; ++gi)
            #pragma unroll
            for (int ci = 0; ci < 8; ++ci)
                atomicAdd(&g_num[(bh * 64 + g0 + gi) * 32 + c0 + ci], acc[gi][ci]);
        if (c0 == 0)
            #pragma unroll
            for (int j = 0; j < 8; ++j) atomicAdd(&g_den[bh * 64 + g0 + j], dacc[j]);
    }
}

// ---------------- K3: slice_att -> qkv -> SDPA -> fold Wout -> g_Mb -------------
__global__ __launch_bounds__(256) void k3(const float* __restrict__ Wqkv,
                                          const float* __restrict__ Wout) {
    __shared__ float S[11264];
    float* sa = S;
    float* wq = S + 2048;
    float* qs = S + 5120;
    float* ks2 = S + 7168;
    float* vs = S + 9216;
    float* sc = S;          // overlays sa/wq after phase 2
    float* att = S + 5120;  // overlays qs after phase 4
    const int bh = blockIdx.x, b = bh >> 3, h = bh & 7;
    const int tid = threadIdx.x;
    for (int i = tid; i < 3072; i += 256) wq[i] = Wqkv[i];
    #pragma unroll
    for (int c = 0; c < 8; ++c) {
        int idx = tid * 8 + c;
        sa[idx] = g_num[bh * 2048 + idx] / (g_den[bh * 64 + (idx >> 5)] + 1e-5f);
    }
    __syncthreads();
    for (int t = tid; t < 6144; t += 256) {
        int g = t & 63, j = t >> 6;
        float s2 = 0.f;
        #pragma unroll
        for (int c = 0; c < 32; ++c) s2 += sa[g * 32 + c] * wq[j * 32 + c];
        if (j < 32) qs[g * 32 + j] = s2;
        else if (j < 64) ks2[g * 32 + (j - 32)] = s2;
        else vs[g * 32 + (j - 64)] = s2;
    }
    __syncthreads();
    for (int t = tid; t < 4096; t += 256) {
        int g = t >> 6, kk = t & 63;
        float s2 = 0.f;
        #pragma unroll
        for (int c = 0; c < 32; ++c) s2 += qs[g * 32 + c] * ks2[kk * 32 + c];
        sc[g * 65 + kk] = s2 * 0.17677669529663687f;
    }
    __syncthreads();
    if (tid < 64) {
        int g = tid;
        float m = -1e30f;
        #pragma unroll 8
        for (int kk = 0; kk < 64; ++kk) m = fmaxf(m, sc[g * 65 + kk]);
        float ssum = 0.f;
        #pragma unroll 8
        for (int kk = 0; kk < 64; ++kk) {
            float e = __expf(sc[g * 65 + kk] - m);
            sc[g * 65 + kk] = e;
            ssum += e;
        }
        float inv = 1.0f / ssum;
        #pragma unroll 8
        for (int kk = 0; kk < 64; ++kk) sc[g * 65 + kk] *= inv;
    }
    __syncthreads();
    for (int t = tid; t < 2048; t += 256) {
        int g = t >> 5, c = t & 31;
        float a = 0.f;
        #pragma unroll 8
        for (int kk = 0; kk < 64; ++kk) a += sc[g * 65 + kk] * vs[kk * 32 + c];
        att[g * 32 + c] = a;
    }
    __syncthreads();
    int d2 = tid;
    float wl[32];
    #pragma unroll
    for (int c = 0; c < 32; ++c) wl[c] = Wout[d2 * 256 + h * 32 + c];
    for (int g = 0; g < 64; ++g) {
        float s2 = 0.f;
        #pragma unroll
        for (int c = 0; c < 32; ++c) s2 += att[g * 32 + c] * wl[c];
        __nv_bfloat16 h16 = __float2bfloat16(s2);
        __nv_bfloat16 l16 = __float2bfloat16(s2 - __bfloat162float(h16));
        size_t o0 = (size_t)b * 256 * 1536 + (size_t)d2 * 1536 + h * 64 + g;
        g_Mb[o0] = h16;
        g_Mb[o0 + 512] = l16;
        g_Mb[o0 + 1024] = h16;
    }
}

// ---------------- K4: out = sw @ M + bout ([128x128] tile, K'=1536) --------------
__global__ __launch_bounds__(256, 2) void k4(float* __restrict__ out,
                                             const float* __restrict__ bout) {
    extern __shared__ char sm[];
    uint32_t sb = s2u(sm);
    const int tid = threadIdx.x, lane = tid & 31, wid = tid >> 5;
    const int wm = wid & 3, wn = wid >> 2;
    const int y = blockIdx.x;  // 0..1
    const int b = blockIdx.y >> 8, t0 = (blockIdx.y & 255) * 128;
    float* bias = (float*)(sm + 65536);
    if (tid < 128) bias[tid] = bout[y * 128 + tid];

    const __nv_bfloat16* swh = g_swh + (size_t)(b * NN + t0) * 512;
    const __nv_bfloat16* swl = g_swl + (size_t)(b * NN + t0) * 512;
    const __nv_bfloat16* Bsrc = g_Mb + (size_t)b * 256 * 1536 + (size_t)(y * 128) * 1536;

    float acc[2][8][4];
    #pragma unroll
    for (int i = 0; i < 2; ++i)
        #pragma unroll
        for (int j = 0; j < 8; ++j)
            #pragma unroll
            for (int k = 0; k < 4; ++k) acc[i][j][k] = 0.f;

    gemm128<24, 16, 8, 512, 1536>(swh, swl, Bsrc, sb, wm, wn, lane, acc);

    const int q = lane & 3, qr = lane >> 2;
    const int cbl = wn * 64;
    #pragma unroll
    for (int mf = 0; mf < 2; ++mf)
        #pragma unroll
        for (int half = 0; half < 2; ++half) {
            int rl = wm * 32 + mf * 16 + qr + half * 8;
            float* op = out + (size_t)(b * NN + t0 + rl) * 256 + y * 128 + cbl;
            #pragma unroll
            for (int nf = 0; nf < 8; ++nf) {
                float v0 = acc[mf][nf][half * 2 + 0] + bias[cbl + nf * 8 + q * 2 + 0];
                float v1 = acc[mf][nf][half * 2 + 1] + bias[cbl + nf * 8 + q * 2 + 1];
                *(float2*)(op + nf * 8 + q * 2) = make_float2(v0, v1);
            }
        }
}

extern "C" void kernel_launch(void* const* d_in, const int* in_sizes, int n_in,
                              void* d_out, int out_size) {
    const float* x = (const float*)d_in[0];
    const float* Wx = (const float*)d_in[1];
    const float* bx = (const float*)d_in[2];
    const float* Wfx = (const float*)d_in[3];
    const float* bfx = (const float*)d_in[4];
    const float* Wsl = (const float*)d_in[5];
    const float* bsl = (const float*)d_in[6];
    const float* temp = (const float*)d_in[7];
    const float* Wqkv = (const float*)d_in[8];
    const float* Wout = (const float*)d_in[9];
    const float* bout = (const float*)d_in[10];
    float* out = (float*)d_out;

    const int SMEM = 65536 + 1024;
    cudaFuncSetAttribute(k1, cudaFuncAttributeMaxDynamicSharedMemorySize, SMEM);
    cudaFuncSetAttribute(k4, cudaFuncAttributeMaxDynamicSharedMemorySize, SMEM);
    const int SMEM2 = 4 * 13824;  // 55296
    cudaFuncSetAttribute(k2, cudaFuncAttributeMaxDynamicSharedMemorySize, SMEM2);

    k0<<<768, 256>>>(Wx, bx, Wfx, bfx, Wsl, bsl, temp);
    kprep<<<16384, 256>>>(x);
    kzero<<<(2 * 8 * 64 * 32 + 2 * 8 * 64 + 255) / 256, 256>>>();
    k1<<<dim3(6, 512), 256, SMEM>>>();
    k2<<<dim3(32, 16), 256, SMEM2>>>();
    k3<<<16, 256>>>(Wqkv, Wout);
    k4<<<dim3(2, 512), 256, SMEM>>>(out, bout);
}

// round 13
// speedup vs baseline: 1.1913x; 1.0499x over previous
#include <cuda_runtime.h>
#include <cuda_bf16.h>
#include <cstdint>

#define NN 32768
#define SWZ(o) ((o) ^ (((o) >> 3) & 0x70))

__device__ __align__(128) __nv_bfloat16 g_xh[(size_t)2 * NN * 256];
__device__ __align__(128) __nv_bfloat16 g_xl[(size_t)2 * NN * 256];
__device__ __align__(128) __nv_bfloat16 g_B1b[768u * 768];
__device__ __align__(128) float g_bias1[768];
__device__ __align__(128) __nv_bfloat16 g_swh[(size_t)2 * NN * 512];
__device__ __align__(128) __nv_bfloat16 g_swl[(size_t)2 * NN * 512];
__device__ __align__(128) __nv_bfloat16 g_fxh[(size_t)2 * NN * 256];
__device__ __align__(128) __nv_bfloat16 g_fxl[(size_t)2 * NN * 256];
__device__ __align__(128) float g_num[2 * 8 * 64 * 32];
__device__ __align__(128) float g_den[2 * 8 * 64];
__device__ __align__(128) __nv_bfloat16 g_Mb[(size_t)2 * 256 * 1536];

__device__ __forceinline__ uint32_t s2u(const void* p) {
    uint32_t a;
    asm("{ .reg .u64 t; cvta.to.shared.u64 t, %1; cvt.u32.u64 %0, t; }" : "=r"(a) : "l"(p));
    return a;
}
__device__ __forceinline__ void cpa16(uint32_t dst, const void* src) {
    asm volatile("cp.async.cg.shared.global [%0], [%1], 16;" :: "r"(dst), "l"(src));
}
__device__ __forceinline__ void cpa_commit() { asm volatile("cp.async.commit_group;" ::: "memory"); }
template <int N>
__device__ __forceinline__ void cpa_wait() { asm volatile("cp.async.wait_group %0;" :: "n"(N) : "memory"); }

__device__ __forceinline__ void ldsm4(uint32_t* r, uint32_t addr) {
    asm volatile("ldmatrix.sync.aligned.m8n8.x4.shared.b16 {%0,%1,%2,%3}, [%4];"
                 : "=r"(r[0]), "=r"(r[1]), "=r"(r[2]), "=r"(r[3]) : "r"(addr));
}
__device__ __forceinline__ void ldsm4t(uint32_t* r, uint32_t addr) {
    asm volatile("ldmatrix.sync.aligned.m8n8.x4.trans.shared.b16 {%0,%1,%2,%3}, [%4];"
                 : "=r"(r[0]), "=r"(r[1]), "=r"(r[2]), "=r"(r[3]) : "r"(addr));
}
__device__ __forceinline__ void mma_bf16(float* c, const uint32_t* a, uint32_t b0, uint32_t b1) {
    asm volatile("mma.sync.aligned.m16n8k16.row.col.f32.bf16.bf16.f32 "
                 "{%0,%1,%2,%3},{%4,%5,%6,%7},{%8,%9},{%0,%1,%2,%3};"
                 : "+f"(c[0]), "+f"(c[1]), "+f"(c[2]), "+f"(c[3])
                 : "r"(a[0]), "r"(a[1]), "r"(a[2]), "r"(a[3]), "r"(b0), "r"(b1));
}

// one 64-k chunk: warp (wm 0..3, wn 0..1) computes 32x64 of the 128x128 tile
__device__ __forceinline__ void compute_chunk(uint32_t abase, uint32_t bbase, int wm, int wn,
                                              int lane, float (&acc)[2][8][4]) {
    const int l15 = lane & 15, l16 = (lane >> 4) << 4;
    uint32_t arb[2], brb[4];
    int asz[2], bsz[4];
    #pragma unroll
    for (int mf = 0; mf < 2; ++mf) {
        int r = wm * 32 + mf * 16 + l15;
        arb[mf] = abase + r * 128;
        asz[mf] = (r & 7) << 4;
    }
    #pragma unroll
    for (int ng = 0; ng < 4; ++ng) {
        int r = wn * 64 + ng * 16 + l15;
        brb[ng] = bbase + r * 128;
        bsz[ng] = (r & 7) << 4;
    }
    #pragma unroll
    for (int ks = 0; ks < 4; ++ks) {
        uint32_t a[2][4], bq[4][4];
        int cb = ks * 32 + l16;
        #pragma unroll
        for (int mf = 0; mf < 2; ++mf) ldsm4(a[mf], arb[mf] + (cb ^ asz[mf]));
        #pragma unroll
        for (int ng = 0; ng < 4; ++ng) ldsm4(bq[ng], brb[ng] + (cb ^ bsz[ng]));
        #pragma unroll
        for (int mf = 0; mf < 2; ++mf)
            #pragma unroll
            for (int nf = 0; nf < 8; ++nf)
                mma_bf16(acc[mf][nf], a[mf], bq[nf >> 1][nf & 1], bq[nf >> 1][2 + (nf & 1)]);
    }
}

// 2-stage pipelined mainloop with hoisted staging offsets (k1=232us measured).
template <int NCHK, int SPLIT, int AWRAP, int ALD, int BLD>
__device__ __forceinline__ void gemm128(const __nv_bfloat16* __restrict__ Ah,
                                        const __nv_bfloat16* __restrict__ Al,
                                        const __nv_bfloat16* __restrict__ Bsrc,
                                        uint32_t sb, int wm, int wn, int lane,
                                        float (&acc)[2][8][4]) {
    const int tid = threadIdx.x;
    const uint32_t off0 = SWZ((uint32_t)((tid >> 3) * 128 + (tid & 7) * 16));
    const int sA = (tid >> 3) * ALD + (tid & 7) * 8;
    const int sB = (tid >> 3) * BLD + (tid & 7) * 8;

    auto stg = [&](int c) {
        uint32_t base = sb + (c & 1) * 16384;
        const __nv_bfloat16* pa =
            ((c < SPLIT) ? Ah + (c % AWRAP) * 64 : Al + ((c - SPLIT) % AWRAP) * 64) + sA;
        const __nv_bfloat16* pb = Bsrc + (size_t)c * 64 + sB;
        #pragma unroll
        for (int i = 0; i < 4; ++i) cpa16(base + off0 + i * 4096, pa + i * 32 * ALD);
        #pragma unroll
        for (int i = 0; i < 4; ++i)
            cpa16(base + 32768 + off0 + i * 4096, pb + i * 32 * BLD);
        cpa_commit();
    };

    stg(0);
    #pragma unroll 1
    for (int c = 0; c < NCHK; ++c) {
        if (c + 1 < NCHK) {
            stg(c + 1);
            cpa_wait<1>();
        } else {
            cpa_wait<0>();
        }
        __syncthreads();
        uint32_t ab = sb + (c & 1) * 16384;
        compute_chunk(ab, ab + 32768, wm, wn, lane, acc);
        __syncthreads();
    }
}

// ---------------- K0: folded B1 (bf16 hi/lo/hi) + bias ----------------
__global__ void k0(const float* __restrict__ Wx, const float* __restrict__ bx,
                   const float* __restrict__ Wfx, const float* __restrict__ bfx,
                   const float* __restrict__ Wsl, const float* __restrict__ bsl,
                   const float* __restrict__ temp) {
    int col = blockIdx.x, d = threadIdx.x;
    float v;
    if (col < 512) {
        int h = col >> 6, g = col & 63;
        float s = 0.f;
        #pragma unroll
        for (int c = 0; c < 32; ++c) s += Wx[(h * 32 + c) * 256 + d] * Wsl[g * 32 + c];
        float it = 1.0f / temp[h];
        v = s * it;
        if (d == 0) {
            float sb = bsl[g];
            for (int c = 0; c < 32; ++c) sb += bx[h * 32 + c] * Wsl[g * 32 + c];
            g_bias1[col] = sb * it;
        }
    } else {
        v = Wfx[(col - 512) * 256 + d];
        if (d == 0) g_bias1[col] = bfx[col - 512];
    }
    __nv_bfloat16 h16 = __float2bfloat16(v);
    __nv_bfloat16 l16 = __float2bfloat16(v - __bfloat162float(h16));
    g_B1b[(size_t)col * 768 + d] = h16;
    g_B1b[(size_t)col * 768 + 256 + d] = l16;
    g_B1b[(size_t)col * 768 + 512 + d] = h16;
}

__global__ void kprep(const float* __restrict__ x) {
    size_t i = ((size_t)blockIdx.x * 256 + threadIdx.x) * 4;
    float4 v = *(const float4*)(x + i);
    __nv_bfloat162 ha, hb, la, lb;
    ha.x = __float2bfloat16(v.x); ha.y = __float2bfloat16(v.y);
    hb.x = __float2bfloat16(v.z); hb.y = __float2bfloat16(v.w);
    la.x = __float2bfloat16(v.x - __bfloat162float(ha.x));
    la.y = __float2bfloat16(v.y - __bfloat162float(ha.y));
    lb.x = __float2bfloat16(v.z - __bfloat162float(hb.x));
    lb.y = __float2bfloat16(v.w - __bfloat162float(hb.y));
    *(uint2*)&g_xh[i] = make_uint2(*(uint32_t*)&ha, *(uint32_t*)&hb);
    *(uint2*)&g_xl[i] = make_uint2(*(uint32_t*)&la, *(uint32_t*)&lb);
}

__global__ void kzero() {
    int i = blockIdx.x * 256 + threadIdx.x;
    if (i < 2 * 8 * 64 * 32) g_num[i] = 0.f;
    int j = i - 2 * 8 * 64 * 32;
    if (j >= 0 && j < 2 * 8 * 64) g_den[j] = 0.f;
}

// ---------------- K1: [128x128] GEMM over K'=768, fused softmax / fx(bf16 hi/lo) -
__global__ __launch_bounds__(256, 2) void k1() {
    extern __shared__ char sm[];
    uint32_t sb = s2u(sm);
    const int tid = threadIdx.x, lane = tid & 31, wid = tid >> 5;
    const int wm = wid & 3, wn = wid >> 2;
    const int y = blockIdx.x;  // 0..5
    const int b = blockIdx.y >> 8, t0 = (blockIdx.y & 255) * 128;
    float* bias = (float*)(sm + 65536);
    if (tid < 128) bias[tid] = g_bias1[y * 128 + tid];

    const __nv_bfloat16* xh = g_xh + (size_t)(b * NN + t0) * 256;
    const __nv_bfloat16* xl = g_xl + (size_t)(b * NN + t0) * 256;
    const __nv_bfloat16* Bsrc = g_B1b + (size_t)(y * 128) * 768;

    float acc[2][8][4];
    #pragma unroll
    for (int i = 0; i < 2; ++i)
        #pragma unroll
        for (int j = 0; j < 8; ++j)
            #pragma unroll
            for (int k = 0; k < 4; ++k) acc[i][j][k] = 0.f;

    gemm128<12, 8, 4, 256, 768>(xh, xl, Bsrc, sb, wm, wn, lane, acc);

    const int q = lane & 3, qr = lane >> 2;
    const int cbl = wn * 64;
    #pragma unroll
    for (int mf = 0; mf < 2; ++mf)
        #pragma unroll
        for (int half = 0; half < 2; ++half) {
            int rl = wm * 32 + mf * 16 + qr + half * 8;
            size_t rb = (size_t)(b * NN + t0 + rl);
            float v[8][2];
            #pragma unroll
            for (int nf = 0; nf < 8; ++nf) {
                v[nf][0] = acc[mf][nf][half * 2 + 0] + bias[cbl + nf * 8 + q * 2 + 0];
                v[nf][1] = acc[mf][nf][half * 2 + 1] + bias[cbl + nf * 8 + q * 2 + 1];
            }
            if (y < 4) {
                float m = v[0][0];
                #pragma unroll
                for (int nf = 0; nf < 8; ++nf) m = fmaxf(m, fmaxf(v[nf][0], v[nf][1]));
                m = fmaxf(m, __shfl_xor_sync(0xffffffffu, m, 1));
                m = fmaxf(m, __shfl_xor_sync(0xffffffffu, m, 2));
                float s = 0.f;
                #pragma unroll
                for (int nf = 0; nf < 8; ++nf) {
                    v[nf][0] = __expf(v[nf][0] - m);
                    v[nf][1] = __expf(v[nf][1] - m);
                    s += v[nf][0] + v[nf][1];
                }
                s += __shfl_xor_sync(0xffffffffu, s, 1);
                s += __shfl_xor_sync(0xffffffffu, s, 2);
                float inv = 1.0f / s;
                size_t base = rb * 512 + y * 128 + cbl;
                #pragma unroll
                for (int nf = 0; nf < 8; ++nf) {
                    float a = v[nf][0] * inv, bq2 = v[nf][1] * inv;
                    __nv_bfloat162 hp, lp;
                    hp.x = __float2bfloat16(a); hp.y = __float2bfloat16(bq2);
                    lp.x = __float2bfloat16(a - __bfloat162float(hp.x));
                    lp.y = __float2bfloat16(bq2 - __bfloat162float(hp.y));
                    *(uint32_t*)&g_swh[base + nf * 8 + q * 2] = *(uint32_t*)&hp;
                    *(uint32_t*)&g_swl[base + nf * 8 + q * 2] = *(uint32_t*)&lp;
                }
            } else {
                size_t base = rb * 256 + (y - 4) * 128 + cbl;
                #pragma unroll
                for (int nf = 0; nf < 8; ++nf) {
                    __nv_bfloat162 hp, lp;
                    hp.x = __float2bfloat16(v[nf][0]);
                    hp.y = __float2bfloat16(v[nf][1]);
                    lp.x = __float2bfloat16(v[nf][0] - __bfloat162float(hp.x));
                    lp.y = __float2bfloat16(v[nf][1] - __bfloat162float(hp.y));
                    *(uint32_t*)&g_fxh[base + nf * 8 + q * 2] = *(uint32_t*)&hp;
                    *(uint32_t*)&g_fxl[base + nf * 8 + q * 2] = *(uint32_t*)&lp;
                }
            }
        }
}

// ---------------- K2: num = sw^T @ fx via tensor cores (ldmatrix.trans) ----------
// grid (32 kslices, 16 bh); per CTA K=1024 tokens, 32 strips of 32.
// smem per stage (14336B): [swh 32x144][swl 32x144][fxh 32x80][fxl 32x80]
__global__ __launch_bounds__(256) void k2() {
    extern __shared__ char sm[];
    const uint32_t sb = s2u(sm);
    const int bh = blockIdx.y, b = bh >> 3, h = bh & 7;
    const int n0 = blockIdx.x * 1024;
    const int tid = threadIdx.x, lane = tid & 31, wid = tid >> 5;
    const int mt = wid & 3, np = wid >> 2;  // warp owns m-tile (16 g) x n-pair (16 c)

    // staging assignments
    const int rr = tid >> 3, p8 = tid & 7;               // sw: row rr, 16B chunk p8
    const int fr = (tid & 127) >> 2, fp = tid & 3;       // fx: row fr, chunk fp
    const int fsel = tid >> 7;                           // 0: fxh, 1: fxl
    const uint32_t d_swh = sb + rr * 144 + p8 * 16;
    const uint32_t d_swl = d_swh + 4608;
    const uint32_t d_fx = sb + 9216 + fsel * 2560 + fr * 80 + fp * 16;
    const __nv_bfloat16* s_swh = &g_swh[((size_t)(b * NN + n0 + rr)) * 512 + h * 64 + p8 * 8];
    const __nv_bfloat16* s_swl = &g_swl[((size_t)(b * NN + n0 + rr)) * 512 + h * 64 + p8 * 8];
    const __nv_bfloat16* s_fx =
        (fsel ? g_fxl : g_fxh) + ((size_t)(b * NN + n0 + fr)) * 256 + h * 32 + fp * 8;

    auto stg = [&](int s) {
        uint32_t so = (s & 3) * 14336;
        cpa16(d_swh + so, s_swh + (size_t)s * 32 * 512);
        cpa16(d_swl + so, s_swl + (size_t)s * 32 * 512);
        cpa16(d_fx + so, s_fx + (size_t)s * 32 * 256);
        cpa_commit();
    };

    // ldmatrix.trans address offsets (memory is [token(k)][feature]):
    //   row = (l&7) + ((l>>4)&1)*8 ; col = tile_base + ((l>>3)&1)*8
    const uint32_t a_off = (uint32_t)(((lane & 7) + ((lane >> 4) & 1) * 8) * 144 +
                                      (mt * 16 + ((lane >> 3) & 1) * 8) * 2);
    const uint32_t b_off = (uint32_t)(9216 + ((lane & 7) + ((lane >> 4) & 1) * 8) * 80 +
                                      (np * 16 + ((lane >> 3) & 1) * 8) * 2);
    const int dg = mt * 16 + (lane & 15);
    const int dr0 = (lane >> 4) * 16;

    float acc[2][4] = {{0.f, 0.f, 0.f, 0.f}, {0.f, 0.f, 0.f, 0.f}};
    float dden = 0.f;

    stg(0); stg(1); stg(2);
    #pragma unroll 1
    for (int c = 0; c < 32; ++c) {
        cpa_wait<2>();
        __syncthreads();
        if (c + 3 < 32) stg(c + 3); else cpa_commit();
        const uint32_t st = sb + (c & 3) * 14336;
        #pragma unroll
        for (int s16 = 0; s16 < 2; ++s16) {
            uint32_t ah[4], al[4], bhf[4], blf[4];
            ldsm4t(ah, st + a_off + s16 * 2304);
            ldsm4t(al, st + a_off + 4608 + s16 * 2304);
            ldsm4t(bhf, st + b_off + s16 * 1280);
            ldsm4t(blf, st + b_off + 2560 + s16 * 1280);
            #pragma unroll
            for (int nt = 0; nt < 2; ++nt) {
                mma_bf16(acc[nt], ah, bhf[nt], bhf[2 + nt]);
                mma_bf16(acc[nt], ah, blf[nt], blf[2 + nt]);
                mma_bf16(acc[nt], al, bhf[nt], bhf[2 + nt]);
            }
        }
        if (np == 0) {
            const char* sp = sm + (c & 3) * 14336;
            float ds = 0.f;
            #pragma unroll
            for (int r = 0; r < 16; ++r) {
                int row = dr0 + r;
                ds += __bfloat162float(*(const __nv_bfloat16*)(sp + row * 144 + dg * 2));
                ds += __bfloat162float(*(const __nv_bfloat16*)(sp + 4608 + row * 144 + dg * 2));
            }
            dden += ds;
        }
    }
    dden += __shfl_xor_sync(0xffffffffu, dden, 16);
    if (np == 0 && lane < 16) atomicAdd(&g_den[bh * 64 + dg], dden);
    #pragma unroll
    for (int nt = 0; nt < 2; ++nt)
        #pragma unroll
        for (int j = 0; j < 4; ++j) {
            int g = mt * 16 + (lane >> 2) + (j >> 1) * 8;
            int cc = np * 16 + nt * 8 + (lane & 3) * 2 + (j & 1);
            atomicAdd(&g_num[(bh * 64 + g) * 32 + cc], acc[nt][j]);
        }
}

// ---------------- K3: slice_att -> qkv -> SDPA -> fold Wout -> g_Mb -------------
__global__ __launch_bounds__(256) void k3(const float* __restrict__ Wqkv,
                                          const float* __restrict__ Wout) {
    __shared__ float S[11264];
    float* sa = S;
    float* wq = S + 2048;
    float* qs = S + 5120;
    float* ks2 = S + 7168;
    float* vs = S + 9216;
    float* sc = S;
    float* att = S + 5120;
    const int bh = blockIdx.x, b = bh >> 3, h = bh & 7;
    const int tid = threadIdx.x;
    for (int i = tid; i < 3072; i += 256) wq[i] = Wqkv[i];
    #pragma unroll
    for (int c = 0; c < 8; ++c) {
        int idx = tid * 8 + c;
        sa[idx] = g_num[bh * 2048 + idx] / (g_den[bh * 64 + (idx >> 5)] + 1e-5f);
    }
    __syncthreads();
    for (int t = tid; t < 6144; t += 256) {
        int g = t & 63, j = t >> 6;
        float s2 = 0.f;
        #pragma unroll
        for (int c = 0; c < 32; ++c) s2 += sa[g * 32 + c] * wq[j * 32 + c];
        if (j < 32) qs[g * 32 + j] = s2;
        else if (j < 64) ks2[g * 32 + (j - 32)] = s2;
        else vs[g * 32 + (j - 64)] = s2;
    }
    __syncthreads();
    for (int t = tid; t < 4096; t += 256) {
        int g = t >> 6, kk = t & 63;
        float s2 = 0.f;
        #pragma unroll
        for (int c = 0; c < 32; ++c) s2 += qs[g * 32 + c] * ks2[kk * 32 + c];
        sc[g * 65 + kk] = s2 * 0.17677669529663687f;
    }
    __syncthreads();
    if (tid < 64) {
        int g = tid;
        float m = -1e30f;
        #pragma unroll 8
        for (int kk = 0; kk < 64; ++kk) m = fmaxf(m, sc[g * 65 + kk]);
        float ssum = 0.f;
        #pragma unroll 8
        for (int kk = 0; kk < 64; ++kk) {
            float e = __expf(sc[g * 65 + kk] - m);
            sc[g * 65 + kk] = e;
            ssum += e;
        }
        float inv = 1.0f / ssum;
        #pragma unroll 8
        for (int kk = 0; kk < 64; ++kk) sc[g * 65 + kk] *= inv;
    }
    __syncthreads();
    for (int t = tid; t < 2048; t += 256) {
        int g = t >> 5, c = t & 31;
        float a = 0.f;
        #pragma unroll 8
        for (int kk = 0; kk < 64; ++kk) a += sc[g * 65 + kk] * vs[kk * 32 + c];
        att[g * 32 + c] = a;
    }
    __syncthreads();
    int d2 = tid;
    float wl[32];
    #pragma unroll
    for (int c = 0; c < 32; ++c) wl[c] = Wout[d2 * 256 + h * 32 + c];
    for (int g = 0; g < 64; ++g) {
        float s2 = 0.f;
        #pragma unroll
        for (int c = 0; c < 32; ++c) s2 += att[g * 32 + c] * wl[c];
        __nv_bfloat16 h16 = __float2bfloat16(s2);
        __nv_bfloat16 l16 = __float2bfloat16(s2 - __bfloat162float(h16));
        size_t o0 = (size_t)b * 256 * 1536 + (size_t)d2 * 1536 + h * 64 + g;
        g_Mb[o0] = h16;
        g_Mb[o0 + 512] = l16;
        g_Mb[o0 + 1024] = h16;
    }
}

// ---------------- K4: out = sw @ M + bout ([128x128] tile, K'=1536) --------------
__global__ __launch_bounds__(256, 2) void k4(float* __restrict__ out,
                                             const float* __restrict__ bout) {
    extern __shared__ char sm[];
    uint32_t sb = s2u(sm);
    const int tid = threadIdx.x, lane = tid & 31, wid = tid >> 5;
    const int wm = wid & 3, wn = wid >> 2;
    const int y = blockIdx.x;  // 0..1
    const int b = blockIdx.y >> 8, t0 = (blockIdx.y & 255) * 128;
    float* bias = (float*)(sm + 65536);
    if (tid < 128) bias[tid] = bout[y * 128 + tid];

    const __nv_bfloat16* swh = g_swh + (size_t)(b * NN + t0) * 512;
    const __nv_bfloat16* swl = g_swl + (size_t)(b * NN + t0) * 512;
    const __nv_bfloat16* Bsrc = g_Mb + (size_t)b * 256 * 1536 + (size_t)(y * 128) * 1536;

    float acc[2][8][4];
    #pragma unroll
    for (int i = 0; i < 2; ++i)
        #pragma unroll
        for (int j = 0; j < 8; ++j)
            #pragma unroll
            for (int k = 0; k < 4; ++k) acc[i][j][k] = 0.f;

    gemm128<24, 16, 8, 512, 1536>(swh, swl, Bsrc, sb, wm, wn, lane, acc);

    const int q = lane & 3, qr = lane >> 2;
    const int cbl = wn * 64;
    #pragma unroll
    for (int mf = 0; mf < 2; ++mf)
        #pragma unroll
        for (int half = 0; half < 2; ++half) {
            int rl = wm * 32 + mf * 16 + qr + half * 8;
            float* op = out + (size_t)(b * NN + t0 + rl) * 256 + y * 128 + cbl;
            #pragma unroll
            for (int nf = 0; nf < 8; ++nf) {
                float v0 = acc[mf][nf][half * 2 + 0] + bias[cbl + nf * 8 + q * 2 + 0];
                float v1 = acc[mf][nf][half * 2 + 1] + bias[cbl + nf * 8 + q * 2 + 1];
                *(float2*)(op + nf * 8 + q * 2) = make_float2(v0, v1);
            }
        }
}

extern "C" void kernel_launch(void* const* d_in, const int* in_sizes, int n_in,
                              void* d_out, int out_size) {
    const float* x = (const float*)d_in[0];
    const float* Wx = (const float*)d_in[1];
    const float* bx = (const float*)d_in[2];
    const float* Wfx = (const float*)d_in[3];
    const float* bfx = (const float*)d_in[4];
    const float* Wsl = (const float*)d_in[5];
    const float* bsl = (const float*)d_in[6];
    const float* temp = (const float*)d_in[7];
    const float* Wqkv = (const float*)d_in[8];
    const float* Wout = (const float*)d_in[9];
    const float* bout = (const float*)d_in[10];
    float* out = (float*)d_out;

    const int SMEM = 65536 + 1024;
    cudaFuncSetAttribute(k1, cudaFuncAttributeMaxDynamicSharedMemorySize, SMEM);
    cudaFuncSetAttribute(k4, cudaFuncAttributeMaxDynamicSharedMemorySize, SMEM);
    const int SMEM2 = 4 * 14336;  // 57344
    cudaFuncSetAttribute(k2, cudaFuncAttributeMaxDynamicSharedMemorySize, SMEM2);

    k0<<<768, 256>>>(Wx, bx, Wfx, bfx, Wsl, bsl, temp);
    kprep<<<16384, 256>>>(x);
    kzero<<<(2 * 8 * 64 * 32 + 2 * 8 * 64 + 255) / 256, 256>>>();
    k1<<<dim3(6, 512), 256, SMEM>>>();
    k2<<<dim3(32, 16), 256, SMEM2>>>();
    k3<<<16, 256>>>(Wqkv, Wout);
    k4<<<dim3(2, 512), 256, SMEM>>>(out, bout);
}

// round 14
// speedup vs baseline: 1.1928x; 1.0012x over previous
#include <cuda_runtime.h>
#include <cuda_bf16.h>
#include <cstdint>

#define NN 32768
#define SWZ(o) ((o) ^ (((o) >> 3) & 0x70))

__device__ __align__(128) __nv_bfloat16 g_xh[(size_t)2 * NN * 256];
__device__ __align__(128) __nv_bfloat16 g_xl[(size_t)2 * NN * 256];
__device__ __align__(128) __nv_bfloat16 g_B1b[768u * 768];
__device__ __align__(128) float g_bias1[768];
__device__ __align__(128) __nv_bfloat16 g_swh[(size_t)2 * NN * 512];
__device__ __align__(128) __nv_bfloat16 g_swl[(size_t)2 * NN * 512];
__device__ __align__(128) __nv_bfloat16 g_fxh[(size_t)2 * NN * 256];
__device__ __align__(128) __nv_bfloat16 g_fxl[(size_t)2 * NN * 256];
__device__ __align__(128) float g_num[2 * 8 * 64 * 32];
__device__ __align__(128) float g_den[2 * 8 * 64];
__device__ __align__(128) __nv_bfloat16 g_Mb[(size_t)2 * 256 * 1536];

__device__ __forceinline__ uint32_t s2u(const void* p) {
    uint32_t a;
    asm("{ .reg .u64 t; cvta.to.shared.u64 t, %1; cvt.u32.u64 %0, t; }" : "=r"(a) : "l"(p));
    return a;
}
__device__ __forceinline__ void cpa16(uint32_t dst, const void* src) {
    asm volatile("cp.async.cg.shared.global [%0], [%1], 16;" :: "r"(dst), "l"(src));
}
__device__ __forceinline__ void cpa_commit() { asm volatile("cp.async.commit_group;" ::: "memory"); }
template <int N>
__device__ __forceinline__ void cpa_wait() { asm volatile("cp.async.wait_group %0;" :: "n"(N) : "memory"); }

__device__ __forceinline__ void ldsm4(uint32_t* r, uint32_t addr) {
    asm volatile("ldmatrix.sync.aligned.m8n8.x4.shared.b16 {%0,%1,%2,%3}, [%4];"
                 : "=r"(r[0]), "=r"(r[1]), "=r"(r[2]), "=r"(r[3]) : "r"(addr));
}
__device__ __forceinline__ void ldsm4t(uint32_t* r, uint32_t addr) {
    asm volatile("ldmatrix.sync.aligned.m8n8.x4.trans.shared.b16 {%0,%1,%2,%3}, [%4];"
                 : "=r"(r[0]), "=r"(r[1]), "=r"(r[2]), "=r"(r[3]) : "r"(addr));
}
__device__ __forceinline__ void mma_bf16(float* c, const uint32_t* a, uint32_t b0, uint32_t b1) {
    asm volatile("mma.sync.aligned.m16n8k16.row.col.f32.bf16.bf16.f32 "
                 "{%0,%1,%2,%3},{%4,%5,%6,%7},{%8,%9},{%0,%1,%2,%3};"
                 : "+f"(c[0]), "+f"(c[1]), "+f"(c[2]), "+f"(c[3])
                 : "r"(a[0]), "r"(a[1]), "r"(a[2]), "r"(a[3]), "r"(b0), "r"(b1));
}

// one 64-k chunk: warp (wm 0..3, wn 0..1) computes 32x64 of the 128x128 tile
__device__ __forceinline__ void compute_chunk(uint32_t abase, uint32_t bbase, int wm, int wn,
                                              int lane, float (&acc)[2][8][4]) {
    const int l15 = lane & 15, l16 = (lane >> 4) << 4;
    uint32_t arb[2], brb[4];
    int asz[2], bsz[4];
    #pragma unroll
    for (int mf = 0; mf < 2; ++mf) {
        int r = wm * 32 + mf * 16 + l15;
        arb[mf] = abase + r * 128;
        asz[mf] = (r & 7) << 4;
    }
    #pragma unroll
    for (int ng = 0; ng < 4; ++ng) {
        int r = wn * 64 + ng * 16 + l15;
        brb[ng] = bbase + r * 128;
        bsz[ng] = (r & 7) << 4;
    }
    #pragma unroll
    for (int ks = 0; ks < 4; ++ks) {
        uint32_t a[2][4], bq[4][4];
        int cb = ks * 32 + l16;
        #pragma unroll
        for (int mf = 0; mf < 2; ++mf) ldsm4(a[mf], arb[mf] + (cb ^ asz[mf]));
        #pragma unroll
        for (int ng = 0; ng < 4; ++ng) ldsm4(bq[ng], brb[ng] + (cb ^ bsz[ng]));
        #pragma unroll
        for (int mf = 0; mf < 2; ++mf)
            #pragma unroll
            for (int nf = 0; nf < 8; ++nf)
                mma_bf16(acc[mf][nf], a[mf], bq[nf >> 1][nf & 1], bq[nf >> 1][2 + (nf & 1)]);
    }
}

// 2-stage pipelined mainloop with hoisted staging offsets (k1=232-244us measured).
template <int NCHK, int SPLIT, int AWRAP, int ALD, int BLD>
__device__ __forceinline__ void gemm128(const __nv_bfloat16* __restrict__ Ah,
                                        const __nv_bfloat16* __restrict__ Al,
                                        const __nv_bfloat16* __restrict__ Bsrc,
                                        uint32_t sb, int wm, int wn, int lane,
                                        float (&acc)[2][8][4]) {
    const int tid = threadIdx.x;
    const uint32_t off0 = SWZ((uint32_t)((tid >> 3) * 128 + (tid & 7) * 16));
    const int sA = (tid >> 3) * ALD + (tid & 7) * 8;
    const int sB = (tid >> 3) * BLD + (tid & 7) * 8;

    auto stg = [&](int c) {
        uint32_t base = sb + (c & 1) * 16384;
        const __nv_bfloat16* pa =
            ((c < SPLIT) ? Ah + (c % AWRAP) * 64 : Al + ((c - SPLIT) % AWRAP) * 64) + sA;
        const __nv_bfloat16* pb = Bsrc + (size_t)c * 64 + sB;
        #pragma unroll
        for (int i = 0; i < 4; ++i) cpa16(base + off0 + i * 4096, pa + i * 32 * ALD);
        #pragma unroll
        for (int i = 0; i < 4; ++i)
            cpa16(base + 32768 + off0 + i * 4096, pb + i * 32 * BLD);
        cpa_commit();
    };

    stg(0);
    #pragma unroll 1
    for (int c = 0; c < NCHK; ++c) {
        if (c + 1 < NCHK) {
            stg(c + 1);
            cpa_wait<1>();
        } else {
            cpa_wait<0>();
        }
        __syncthreads();
        uint32_t ab = sb + (c & 1) * 16384;
        compute_chunk(ab, ab + 32768, wm, wn, lane, acc);
        __syncthreads();
    }
}

// ---------------- K0: folded B1 (bf16 hi/lo/hi) + bias + zero-scratch ----------
__global__ void k0(const float* __restrict__ Wx, const float* __restrict__ bx,
                   const float* __restrict__ Wfx, const float* __restrict__ bfx,
                   const float* __restrict__ Wsl, const float* __restrict__ bsl,
                   const float* __restrict__ temp) {
    int col = blockIdx.x, d = threadIdx.x;
    {   // fold in scratch zeroing (replaces kzero launch)
        int idx = col * 256 + d;
        if (idx < 2 * 8 * 64 * 32) g_num[idx] = 0.f;
        if (idx < 2 * 8 * 64) g_den[idx] = 0.f;
    }
    float v;
    if (col < 512) {
        int h = col >> 6, g = col & 63;
        float s = 0.f;
        #pragma unroll
        for (int c = 0; c < 32; ++c) s += Wx[(h * 32 + c) * 256 + d] * Wsl[g * 32 + c];
        float it = 1.0f / temp[h];
        v = s * it;
        if (d == 0) {
            float sb = bsl[g];
            for (int c = 0; c < 32; ++c) sb += bx[h * 32 + c] * Wsl[g * 32 + c];
            g_bias1[col] = sb * it;
        }
    } else {
        v = Wfx[(col - 512) * 256 + d];
        if (d == 0) g_bias1[col] = bfx[col - 512];
    }
    __nv_bfloat16 h16 = __float2bfloat16(v);
    __nv_bfloat16 l16 = __float2bfloat16(v - __bfloat162float(h16));
    g_B1b[(size_t)col * 768 + d] = h16;
    g_B1b[(size_t)col * 768 + 256 + d] = l16;
    g_B1b[(size_t)col * 768 + 512 + d] = h16;
}

__global__ void kprep(const float* __restrict__ x) {
    size_t i = ((size_t)blockIdx.x * 256 + threadIdx.x) * 4;
    float4 v = *(const float4*)(x + i);
    __nv_bfloat162 ha, hb, la, lb;
    ha.x = __float2bfloat16(v.x); ha.y = __float2bfloat16(v.y);
    hb.x = __float2bfloat16(v.z); hb.y = __float2bfloat16(v.w);
    la.x = __float2bfloat16(v.x - __bfloat162float(ha.x));
    la.y = __float2bfloat16(v.y - __bfloat162float(ha.y));
    lb.x = __float2bfloat16(v.z - __bfloat162float(hb.x));
    lb.y = __float2bfloat16(v.w - __bfloat162float(hb.y));
    *(uint2*)&g_xh[i] = make_uint2(*(uint32_t*)&ha, *(uint32_t*)&hb);
    *(uint2*)&g_xl[i] = make_uint2(*(uint32_t*)&la, *(uint32_t*)&lb);
}

// ---------------- K1: [128x128] GEMM over K'=768, fused softmax / fx(bf16 hi/lo) -
__global__ __launch_bounds__(256, 2) void k1() {
    extern __shared__ char sm[];
    uint32_t sb = s2u(sm);
    const int tid = threadIdx.x, lane = tid & 31, wid = tid >> 5;
    const int wm = wid & 3, wn = wid >> 2;
    const int y = blockIdx.x;  // 0..5
    const int b = blockIdx.y >> 8, t0 = (blockIdx.y & 255) * 128;
    float* bias = (float*)(sm + 65536);
    if (tid < 128) bias[tid] = g_bias1[y * 128 + tid];

    const __nv_bfloat16* xh = g_xh + (size_t)(b * NN + t0) * 256;
    const __nv_bfloat16* xl = g_xl + (size_t)(b * NN + t0) * 256;
    const __nv_bfloat16* Bsrc = g_B1b + (size_t)(y * 128) * 768;

    float acc[2][8][4];
    #pragma unroll
    for (int i = 0; i < 2; ++i)
        #pragma unroll
        for (int j = 0; j < 8; ++j)
            #pragma unroll
            for (int k = 0; k < 4; ++k) acc[i][j][k] = 0.f;

    gemm128<12, 8, 4, 256, 768>(xh, xl, Bsrc, sb, wm, wn, lane, acc);

    const int q = lane & 3, qr = lane >> 2;
    const int cbl = wn * 64;
    #pragma unroll
    for (int mf = 0; mf < 2; ++mf)
        #pragma unroll
        for (int half = 0; half < 2; ++half) {
            int rl = wm * 32 + mf * 16 + qr + half * 8;
            size_t rb = (size_t)(b * NN + t0 + rl);
            float v[8][2];
            #pragma unroll
            for (int nf = 0; nf < 8; ++nf) {
                v[nf][0] = acc[mf][nf][half * 2 + 0] + bias[cbl + nf * 8 + q * 2 + 0];
                v[nf][1] = acc[mf][nf][half * 2 + 1] + bias[cbl + nf * 8 + q * 2 + 1];
            }
            if (y < 4) {
                float m = v[0][0];
                #pragma unroll
                for (int nf = 0; nf < 8; ++nf) m = fmaxf(m, fmaxf(v[nf][0], v[nf][1]));
                m = fmaxf(m, __shfl_xor_sync(0xffffffffu, m, 1));
                m = fmaxf(m, __shfl_xor_sync(0xffffffffu, m, 2));
                float s = 0.f;
                #pragma unroll
                for (int nf = 0; nf < 8; ++nf) {
                    v[nf][0] = __expf(v[nf][0] - m);
                    v[nf][1] = __expf(v[nf][1] - m);
                    s += v[nf][0] + v[nf][1];
                }
                s += __shfl_xor_sync(0xffffffffu, s, 1);
                s += __shfl_xor_sync(0xffffffffu, s, 2);
                float inv = 1.0f / s;
                size_t base = rb * 512 + y * 128 + cbl;
                #pragma unroll
                for (int nf = 0; nf < 8; ++nf) {
                    float a = v[nf][0] * inv, bq2 = v[nf][1] * inv;
                    __nv_bfloat162 hp, lp;
                    hp.x = __float2bfloat16(a); hp.y = __float2bfloat16(bq2);
                    lp.x = __float2bfloat16(a - __bfloat162float(hp.x));
                    lp.y = __float2bfloat16(bq2 - __bfloat162float(hp.y));
                    *(uint32_t*)&g_swh[base + nf * 8 + q * 2] = *(uint32_t*)&hp;
                    *(uint32_t*)&g_swl[base + nf * 8 + q * 2] = *(uint32_t*)&lp;
                }
            } else {
                size_t base = rb * 256 + (y - 4) * 128 + cbl;
                #pragma unroll
                for (int nf = 0; nf < 8; ++nf) {
                    __nv_bfloat162 hp, lp;
                    hp.x = __float2bfloat16(v[nf][0]);
                    hp.y = __float2bfloat16(v[nf][1]);
                    lp.x = __float2bfloat16(v[nf][0] - __bfloat162float(hp.x));
                    lp.y = __float2bfloat16(v[nf][1] - __bfloat162float(hp.y));
                    *(uint32_t*)&g_fxh[base + nf * 8 + q * 2] = *(uint32_t*)&hp;
                    *(uint32_t*)&g_fxl[base + nf * 8 + q * 2] = *(uint32_t*)&lp;
                }
            }
        }
}

// ---------------- K2: num = sw^T @ fx via tensor cores (ldmatrix.trans) ----------
// grid (64 kslices, 16 bh); per CTA K=512 tokens, 16 strips of 32.
__global__ __launch_bounds__(256) void k2() {
    extern __shared__ char sm[];
    const uint32_t sb = s2u(sm);
    const int bh = blockIdx.y, b = bh >> 3, h = bh & 7;
    const int n0 = blockIdx.x * 512;
    const int tid = threadIdx.x, lane = tid & 31, wid = tid >> 5;
    const int mt = wid & 3, np = wid >> 2;

    const int rr = tid >> 3, p8 = tid & 7;
    const int fr = (tid & 127) >> 2, fp = tid & 3;
    const int fsel = tid >> 7;
    const uint32_t d_swh = sb + rr * 144 + p8 * 16;
    const uint32_t d_swl = d_swh + 4608;
    const uint32_t d_fx = sb + 9216 + fsel * 2560 + fr * 80 + fp * 16;
    const __nv_bfloat16* s_swh = &g_swh[((size_t)(b * NN + n0 + rr)) * 512 + h * 64 + p8 * 8];
    const __nv_bfloat16* s_swl = &g_swl[((size_t)(b * NN + n0 + rr)) * 512 + h * 64 + p8 * 8];
    const __nv_bfloat16* s_fx =
        (fsel ? g_fxl : g_fxh) + ((size_t)(b * NN + n0 + fr)) * 256 + h * 32 + fp * 8;

    auto stg = [&](int s) {
        uint32_t so = (s & 3) * 14336;
        cpa16(d_swh + so, s_swh + (size_t)s * 32 * 512);
        cpa16(d_swl + so, s_swl + (size_t)s * 32 * 512);
        cpa16(d_fx + so, s_fx + (size_t)s * 32 * 256);
        cpa_commit();
    };

    const uint32_t a_off = (uint32_t)(((lane & 7) + ((lane >> 4) & 1) * 8) * 144 +
                                      (mt * 16 + ((lane >> 3) & 1) * 8) * 2);
    const uint32_t b_off = (uint32_t)(9216 + ((lane & 7) + ((lane >> 4) & 1) * 8) * 80 +
                                      (np * 16 + ((lane >> 3) & 1) * 8) * 2);
    const int dg = mt * 16 + (lane & 15);
    const int dr0 = (lane >> 4) * 16;

    float acc[2][4] = {{0.f, 0.f, 0.f, 0.f}, {0.f, 0.f, 0.f, 0.f}};
    float dden = 0.f;

    stg(0); stg(1); stg(2);
    #pragma unroll 1
    for (int c = 0; c < 16; ++c) {
        cpa_wait<2>();
        __syncthreads();
        if (c + 3 < 16) stg(c + 3); else cpa_commit();
        const uint32_t st = sb + (c & 3) * 14336;
        #pragma unroll
        for (int s16 = 0; s16 < 2; ++s16) {
            uint32_t ah[4], al[4], bhf[4], blf[4];
            ldsm4t(ah, st + a_off + s16 * 2304);
            ldsm4t(al, st + a_off + 4608 + s16 * 2304);
            ldsm4t(bhf, st + b_off + s16 * 1280);
            ldsm4t(blf, st + b_off + 2560 + s16 * 1280);
            #pragma unroll
            for (int nt = 0; nt < 2; ++nt) {
                mma_bf16(acc[nt], ah, bhf[nt], bhf[2 + nt]);
                mma_bf16(acc[nt], ah, blf[nt], blf[2 + nt]);
                mma_bf16(acc[nt], al, bhf[nt], bhf[2 + nt]);
            }
        }
        if (np == 0) {
            const char* sp = sm + (c & 3) * 14336;
            float ds = 0.f;
            #pragma unroll
            for (int r = 0; r < 16; ++r) {
                int row = dr0 + r;
                ds += __bfloat162float(*(const __nv_bfloat16*)(sp + row * 144 + dg * 2));
                ds += __bfloat162float(*(const __nv_bfloat16*)(sp + 4608 + row * 144 + dg * 2));
            }
            dden += ds;
        }
    }
    dden += __shfl_xor_sync(0xffffffffu, dden, 16);
    if (np == 0 && lane < 16) atomicAdd(&g_den[bh * 64 + dg], dden);
    #pragma unroll
    for (int nt = 0; nt < 2; ++nt)
        #pragma unroll
        for (int j = 0; j < 4; ++j) {
            int g = mt * 16 + (lane >> 2) + (j >> 1) * 8;
            int cc = np * 16 + nt * 8 + (lane & 3) * 2 + (j & 1);
            atomicAdd(&g_num[(bh * 64 + g) * 32 + cc], acc[nt][j]);
        }
}

// ---------------- K3: slice_att -> qkv -> SDPA -> fold Wout -> g_Mb -------------
__global__ __launch_bounds__(256) void k3(const float* __restrict__ Wqkv,
                                          const float* __restrict__ Wout) {
    __shared__ float S[11264];
    float* sa = S;
    float* wq = S + 2048;
    float* qs = S + 5120;
    float* ks2 = S + 7168;
    float* vs = S + 9216;
    float* sc = S;
    float* att = S + 5120;
    const int bh = blockIdx.x, b = bh >> 3, h = bh & 7;
    const int tid = threadIdx.x;
    for (int i = tid; i < 3072; i += 256) wq[i] = Wqkv[i];
    #pragma unroll
    for (int c = 0; c < 8; ++c) {
        int idx = tid * 8 + c;
        sa[idx] = g_num[bh * 2048 + idx] / (g_den[bh * 64 + (idx >> 5)] + 1e-5f);
    }
    __syncthreads();
    for (int t = tid; t < 6144; t += 256) {
        int g = t & 63, j = t >> 6;
        float s2 = 0.f;
        #pragma unroll
        for (int c = 0; c < 32; ++c) s2 += sa[g * 32 + c] * wq[j * 32 + c];
        if (j < 32) qs[g * 32 + j] = s2;
        else if (j < 64) ks2[g * 32 + (j - 32)] = s2;
        else vs[g * 32 + (j - 64)] = s2;
    }
    __syncthreads();
    for (int t = tid; t < 4096; t += 256) {
        int g = t >> 6, kk = t & 63;
        float s2 = 0.f;
        #pragma unroll
        for (int c = 0; c < 32; ++c) s2 += qs[g * 32 + c] * ks2[kk * 32 + c];
        sc[g * 65 + kk] = s2 * 0.17677669529663687f;
    }
    __syncthreads();
    if (tid < 64) {
        int g = tid;
        float m = -1e30f;
        #pragma unroll 8
        for (int kk = 0; kk < 64; ++kk) m = fmaxf(m, sc[g * 65 + kk]);
        float ssum = 0.f;
        #pragma unroll 8
        for (int kk = 0; kk < 64; ++kk) {
            float e = __expf(sc[g * 65 + kk] - m);
            sc[g * 65 + kk] = e;
            ssum += e;
        }
        float inv = 1.0f / ssum;
        #pragma unroll 8
        for (int kk = 0; kk < 64; ++kk) sc[g * 65 + kk] *= inv;
    }
    __syncthreads();
    for (int t = tid; t < 2048; t += 256) {
        int g = t >> 5, c = t & 31;
        float a = 0.f;
        #pragma unroll 8
        for (int kk = 0; kk < 64; ++kk) a += sc[g * 65 + kk] * vs[kk * 32 + c];
        att[g * 32 + c] = a;
    }
    __syncthreads();
    int d2 = tid;
    float wl[32];
    #pragma unroll
    for (int c = 0; c < 32; ++c) wl[c] = Wout[d2 * 256 + h * 32 + c];
    for (int g = 0; g < 64; ++g) {
        float s2 = 0.f;
        #pragma unroll
        for (int c = 0; c < 32; ++c) s2 += att[g * 32 + c] * wl[c];
        __nv_bfloat16 h16 = __float2bfloat16(s2);
        __nv_bfloat16 l16 = __float2bfloat16(s2 - __bfloat162float(h16));
        size_t o0 = (size_t)b * 256 * 1536 + (size_t)d2 * 1536 + h * 64 + g;
        g_Mb[o0] = h16;
        g_Mb[o0 + 512] = l16;
        g_Mb[o0 + 1024] = h16;
    }
}

// ---------------- K4: out = sw @ M + bout ([128x128] tile, K'=1536) --------------
__global__ __launch_bounds__(256, 2) void k4(float* __restrict__ out,
                                             const float* __restrict__ bout) {
    extern __shared__ char sm[];
    uint32_t sb = s2u(sm);
    const int tid = threadIdx.x, lane = tid & 31, wid = tid >> 5;
    const int wm = wid & 3, wn = wid >> 2;
    const int y = blockIdx.x;  // 0..1
    const int b = blockIdx.y >> 8, t0 = (blockIdx.y & 255) * 128;
    float* bias = (float*)(sm + 65536);
    if (tid < 128) bias[tid] = bout[y * 128 + tid];

    const __nv_bfloat16* swh = g_swh + (size_t)(b * NN + t0) * 512;
    const __nv_bfloat16* swl = g_swl + (size_t)(b * NN + t0) * 512;
    const __nv_bfloat16* Bsrc = g_Mb + (size_t)b * 256 * 1536 + (size_t)(y * 128) * 1536;

    float acc[2][8][4];
    #pragma unroll
    for (int i = 0; i < 2; ++i)
        #pragma unroll
        for (int j = 0; j < 8; ++j)
            #pragma unroll
            for (int k = 0; k < 4; ++k) acc[i][j][k] = 0.f;

    gemm128<24, 16, 8, 512, 1536>(swh, swl, Bsrc, sb, wm, wn, lane, acc);

    const int q = lane & 3, qr = lane >> 2;
    const int cbl = wn * 64;
    #pragma unroll
    for (int mf = 0; mf < 2; ++mf)
        #pragma unroll
        for (int half = 0; half < 2; ++half) {
            int rl = wm * 32 + mf * 16 + qr + half * 8;
            float* op = out + (size_t)(b * NN + t0 + rl) * 256 + y * 128 + cbl;
            #pragma unroll
            for (int nf = 0; nf < 8; ++nf) {
                float v0 = acc[mf][nf][half * 2 + 0] + bias[cbl + nf * 8 + q * 2 + 0];
                float v1 = acc[mf][nf][half * 2 + 1] + bias[cbl + nf * 8 + q * 2 + 1];
                *(float2*)(op + nf * 8 + q * 2) = make_float2(v0, v1);
            }
        }
}

extern "C" void kernel_launch(void* const* d_in, const int* in_sizes, int n_in,
                              void* d_out, int out_size) {
    const float* x = (const float*)d_in[0];
    const float* Wx = (const float*)d_in[1];
    const float* bx = (const float*)d_in[2];
    const float* Wfx = (const float*)d_in[3];
    const float* bfx = (const float*)d_in[4];
    const float* Wsl = (const float*)d_in[5];
    const float* bsl = (const float*)d_in[6];
    const float* temp = (const float*)d_in[7];
    const float* Wqkv = (const float*)d_in[8];
    const float* Wout = (const float*)d_in[9];
    const float* bout = (const float*)d_in[10];
    float* out = (float*)d_out;

    const int SMEM = 65536 + 1024;
    cudaFuncSetAttribute(k1, cudaFuncAttributeMaxDynamicSharedMemorySize, SMEM);
    cudaFuncSetAttribute(k4, cudaFuncAttributeMaxDynamicSharedMemorySize, SMEM);
    const int SMEM2 = 4 * 14336;  // 57344
    cudaFuncSetAttribute(k2, cudaFuncAttributeMaxDynamicSharedMemorySize, SMEM2);

    k0<<<768, 256>>>(Wx, bx, Wfx, bfx, Wsl, bsl, temp);
    kprep<<<16384, 256>>>(x);
    k1<<<dim3(6, 512), 256, SMEM>>>();
    k2<<<dim3(64, 16), 256, SMEM2>>>();
    k3<<<16, 256>>>(Wqkv, Wout);
    k4<<<dim3(2, 512), 256, SMEM>>>(out, bout);
}

// round 15
// speedup vs baseline: 1.2118x; 1.0159x over previous
#include <cuda_runtime.h>
#include <cuda_bf16.h>
#include <cstdint>

#define NN 32768
#define SWZ(o) ((o) ^ (((o) >> 3) & 0x70))

__device__ __align__(128) __nv_bfloat16 g_xh[(size_t)2 * NN * 256];
__device__ __align__(128) __nv_bfloat16 g_xl[(size_t)2 * NN * 256];
__device__ __align__(128) __nv_bfloat16 g_B1b[768u * 768];
__device__ __align__(128) float g_bias1[768];
__device__ __align__(128) __nv_bfloat16 g_swh[(size_t)2 * NN * 512];
__device__ __align__(128) __nv_bfloat16 g_swl[(size_t)2 * NN * 512];
__device__ __align__(128) __nv_bfloat16 g_fxh[(size_t)2 * NN * 256];
__device__ __align__(128) __nv_bfloat16 g_fxl[(size_t)2 * NN * 256];
__device__ __align__(128) float g_num[2 * 8 * 64 * 32];
__device__ __align__(128) float g_den[2 * 8 * 64];
__device__ __align__(128) __nv_bfloat16 g_Mb[(size_t)2 * 256 * 1536];

__device__ __forceinline__ uint32_t s2u(const void* p) {
    uint32_t a;
    asm("{ .reg .u64 t; cvta.to.shared.u64 t, %1; cvt.u32.u64 %0, t; }" : "=r"(a) : "l"(p));
    return a;
}
__device__ __forceinline__ void cpa16(uint32_t dst, const void* src) {
    asm volatile("cp.async.cg.shared.global [%0], [%1], 16;" :: "r"(dst), "l"(src));
}
__device__ __forceinline__ void cpa_commit() { asm volatile("cp.async.commit_group;" ::: "memory"); }
template <int N>
__device__ __forceinline__ void cpa_wait() { asm volatile("cp.async.wait_group %0;" :: "n"(N) : "memory"); }

__device__ __forceinline__ void ldsm4(uint32_t* r, uint32_t addr) {
    asm volatile("ldmatrix.sync.aligned.m8n8.x4.shared.b16 {%0,%1,%2,%3}, [%4];"
                 : "=r"(r[0]), "=r"(r[1]), "=r"(r[2]), "=r"(r[3]) : "r"(addr));
}
__device__ __forceinline__ void ldsm4t(uint32_t* r, uint32_t addr) {
    asm volatile("ldmatrix.sync.aligned.m8n8.x4.trans.shared.b16 {%0,%1,%2,%3}, [%4];"
                 : "=r"(r[0]), "=r"(r[1]), "=r"(r[2]), "=r"(r[3]) : "r"(addr));
}
__device__ __forceinline__ void mma_bf16(float* c, const uint32_t* a, uint32_t b0, uint32_t b1) {
    asm volatile("mma.sync.aligned.m16n8k16.row.col.f32.bf16.bf16.f32 "
                 "{%0,%1,%2,%3},{%4,%5,%6,%7},{%8,%9},{%0,%1,%2,%3};"
                 : "+f"(c[0]), "+f"(c[1]), "+f"(c[2]), "+f"(c[3])
                 : "r"(a[0]), "r"(a[1]), "r"(a[2]), "r"(a[3]), "r"(b0), "r"(b1));
}

// one 64-k chunk: warp (wm 0..3, wn 0..1) computes 32x64 of the 128x128 tile
__device__ __forceinline__ void compute_chunk(uint32_t abase, uint32_t bbase, int wm, int wn,
                                              int lane, float (&acc)[2][8][4]) {
    const int l15 = lane & 15, l16 = (lane >> 4) << 4;
    uint32_t arb[2], brb[4];
    int asz[2], bsz[4];
    #pragma unroll
    for (int mf = 0; mf < 2; ++mf) {
        int r = wm * 32 + mf * 16 + l15;
        arb[mf] = abase + r * 128;
        asz[mf] = (r & 7) << 4;
    }
    #pragma unroll
    for (int ng = 0; ng < 4; ++ng) {
        int r = wn * 64 + ng * 16 + l15;
        brb[ng] = bbase + r * 128;
        bsz[ng] = (r & 7) << 4;
    }
    #pragma unroll
    for (int ks = 0; ks < 4; ++ks) {
        uint32_t a[2][4], bq[4][4];
        int cb = ks * 32 + l16;
        #pragma unroll
        for (int mf = 0; mf < 2; ++mf) ldsm4(a[mf], arb[mf] + (cb ^ asz[mf]));
        #pragma unroll
        for (int ng = 0; ng < 4; ++ng) ldsm4(bq[ng], brb[ng] + (cb ^ bsz[ng]));
        #pragma unroll
        for (int mf = 0; mf < 2; ++mf)
            #pragma unroll
            for (int nf = 0; nf < 8; ++nf)
                mma_bf16(acc[mf][nf], a[mf], bq[nf >> 1][nf & 1], bq[nf >> 1][2 + (nf & 1)]);
    }
}

// 3-stage single-sync pipelined mainloop; stage i = [A 16KB][B 16KB] at sb + i*32768.
template <int NCHK, int SPLIT, int AWRAP, int ALD, int BLD>
__device__ __forceinline__ void gemm128(const __nv_bfloat16* __restrict__ Ah,
                                        const __nv_bfloat16* __restrict__ Al,
                                        const __nv_bfloat16* __restrict__ Bsrc,
                                        uint32_t sb, int wm, int wn, int lane,
                                        float (&acc)[2][8][4]) {
    const int tid = threadIdx.x;
    const uint32_t off0 = SWZ((uint32_t)((tid >> 3) * 128 + (tid & 7) * 16));
    const int sA = (tid >> 3) * ALD + (tid & 7) * 8;
    const int sB = (tid >> 3) * BLD + (tid & 7) * 8;

    auto stg = [&](int c, uint32_t base) {
        const __nv_bfloat16* pa =
            ((c < SPLIT) ? Ah + (c % AWRAP) * 64 : Al + ((c - SPLIT) % AWRAP) * 64) + sA;
        const __nv_bfloat16* pb = Bsrc + (size_t)c * 64 + sB;
        #pragma unroll
        for (int i = 0; i < 4; ++i) cpa16(base + off0 + i * 4096, pa + i * 32 * ALD);
        #pragma unroll
        for (int i = 0; i < 4; ++i)
            cpa16(base + 16384 + off0 + i * 4096, pb + i * 32 * BLD);
        cpa_commit();
    };
    auto step = [&](int c, uint32_t cur, uint32_t nxt) {
        cpa_wait<1>();
        __syncthreads();
        if (c + 2 < NCHK) stg(c + 2, nxt);
        compute_chunk(cur, cur + 16384, wm, wn, lane, acc);
    };

    stg(0, sb);
    stg(1, sb + 32768);
    #pragma unroll 1
    for (int c = 0; c < NCHK; c += 3) {
        step(c, sb, sb + 65536);
        step(c + 1, sb + 32768, sb);
        step(c + 2, sb + 65536, sb + 32768);
    }
}

// ---------------- K0: folded B1 (bf16 hi/lo/hi) + bias + zero-scratch ----------
__global__ void k0(const float* __restrict__ Wx, const float* __restrict__ bx,
                   const float* __restrict__ Wfx, const float* __restrict__ bfx,
                   const float* __restrict__ Wsl, const float* __restrict__ bsl,
                   const float* __restrict__ temp) {
    int col = blockIdx.x, d = threadIdx.x;
    {
        int idx = col * 256 + d;
        if (idx < 2 * 8 * 64 * 32) g_num[idx] = 0.f;
        if (idx < 2 * 8 * 64) g_den[idx] = 0.f;
    }
    float v;
    if (col < 512) {
        int h = col >> 6, g = col & 63;
        float s = 0.f;
        #pragma unroll
        for (int c = 0; c < 32; ++c) s += Wx[(h * 32 + c) * 256 + d] * Wsl[g * 32 + c];
        float it = 1.0f / temp[h];
        v = s * it;
        if (d == 0) {
            float sb = bsl[g];
            for (int c = 0; c < 32; ++c) sb += bx[h * 32 + c] * Wsl[g * 32 + c];
            g_bias1[col] = sb * it;
        }
    } else {
        v = Wfx[(col - 512) * 256 + d];
        if (d == 0) g_bias1[col] = bfx[col - 512];
    }
    __nv_bfloat16 h16 = __float2bfloat16(v);
    __nv_bfloat16 l16 = __float2bfloat16(v - __bfloat162float(h16));
    g_B1b[(size_t)col * 768 + d] = h16;
    g_B1b[(size_t)col * 768 + 256 + d] = l16;
    g_B1b[(size_t)col * 768 + 512 + d] = h16;
}

__global__ void kprep(const float* __restrict__ x) {
    size_t i = ((size_t)blockIdx.x * 256 + threadIdx.x) * 4;
    float4 v = *(const float4*)(x + i);
    __nv_bfloat162 ha, hb, la, lb;
    ha.x = __float2bfloat16(v.x); ha.y = __float2bfloat16(v.y);
    hb.x = __float2bfloat16(v.z); hb.y = __float2bfloat16(v.w);
    la.x = __float2bfloat16(v.x - __bfloat162float(ha.x));
    la.y = __float2bfloat16(v.y - __bfloat162float(ha.y));
    lb.x = __float2bfloat16(v.z - __bfloat162float(hb.x));
    lb.y = __float2bfloat16(v.w - __bfloat162float(hb.y));
    *(uint2*)&g_xh[i] = make_uint2(*(uint32_t*)&ha, *(uint32_t*)&hb);
    *(uint2*)&g_xl[i] = make_uint2(*(uint32_t*)&la, *(uint32_t*)&lb);
}

// ---------------- K1: [128x128] GEMM over K'=768, fused softmax / fx(bf16 hi/lo) -
__global__ __launch_bounds__(256, 2) void k1() {
    extern __shared__ char sm[];
    uint32_t sb = s2u(sm);
    const int tid = threadIdx.x, lane = tid & 31, wid = tid >> 5;
    const int wm = wid & 3, wn = wid >> 2;
    const int y = blockIdx.x;  // 0..5
    const int b = blockIdx.y >> 8, t0 = (blockIdx.y & 255) * 128;
    float* bias = (float*)(sm + 98304);
    if (tid < 128) bias[tid] = g_bias1[y * 128 + tid];

    const __nv_bfloat16* xh = g_xh + (size_t)(b * NN + t0) * 256;
    const __nv_bfloat16* xl = g_xl + (size_t)(b * NN + t0) * 256;
    const __nv_bfloat16* Bsrc = g_B1b + (size_t)(y * 128) * 768;

    float acc[2][8][4];
    #pragma unroll
    for (int i = 0; i < 2; ++i)
        #pragma unroll
        for (int j = 0; j < 8; ++j)
            #pragma unroll
            for (int k = 0; k < 4; ++k) acc[i][j][k] = 0.f;

    gemm128<12, 8, 4, 256, 768>(xh, xl, Bsrc, sb, wm, wn, lane, acc);

    const int q = lane & 3, qr = lane >> 2;
    const int cbl = wn * 64;
    #pragma unroll
    for (int mf = 0; mf < 2; ++mf)
        #pragma unroll
        for (int half = 0; half < 2; ++half) {
            int rl = wm * 32 + mf * 16 + qr + half * 8;
            size_t rb = (size_t)(b * NN + t0 + rl);
            float v[8][2];
            #pragma unroll
            for (int nf = 0; nf < 8; ++nf) {
                v[nf][0] = acc[mf][nf][half * 2 + 0] + bias[cbl + nf * 8 + q * 2 + 0];
                v[nf][1] = acc[mf][nf][half * 2 + 1] + bias[cbl + nf * 8 + q * 2 + 1];
            }
            if (y < 4) {
                float m = v[0][0];
                #pragma unroll
                for (int nf = 0; nf < 8; ++nf) m = fmaxf(m, fmaxf(v[nf][0], v[nf][1]));
                m = fmaxf(m, __shfl_xor_sync(0xffffffffu, m, 1));
                m = fmaxf(m, __shfl_xor_sync(0xffffffffu, m, 2));
                float s = 0.f;
                #pragma unroll
                for (int nf = 0; nf < 8; ++nf) {
                    v[nf][0] = __expf(v[nf][0] - m);
                    v[nf][1] = __expf(v[nf][1] - m);
                    s += v[nf][0] + v[nf][1];
                }
                s += __shfl_xor_sync(0xffffffffu, s, 1);
                s += __shfl_xor_sync(0xffffffffu, s, 2);
                float inv = 1.0f / s;
                size_t base = rb * 512 + y * 128 + cbl;
                #pragma unroll
                for (int nf = 0; nf < 8; ++nf) {
                    float a = v[nf][0] * inv, bq2 = v[nf][1] * inv;
                    __nv_bfloat162 hp, lp;
                    hp.x = __float2bfloat16(a); hp.y = __float2bfloat16(bq2);
                    lp.x = __float2bfloat16(a - __bfloat162float(hp.x));
                    lp.y = __float2bfloat16(bq2 - __bfloat162float(hp.y));
                    *(uint32_t*)&g_swh[base + nf * 8 + q * 2] = *(uint32_t*)&hp;
                    *(uint32_t*)&g_swl[base + nf * 8 + q * 2] = *(uint32_t*)&lp;
                }
            } else {
                size_t base = rb * 256 + (y - 4) * 128 + cbl;
                #pragma unroll
                for (int nf = 0; nf < 8; ++nf) {
                    __nv_bfloat162 hp, lp;
                    hp.x = __float2bfloat16(v[nf][0]);
                    hp.y = __float2bfloat16(v[nf][1]);
                    lp.x = __float2bfloat16(v[nf][0] - __bfloat162float(hp.x));
                    lp.y = __float2bfloat16(v[nf][1] - __bfloat162float(hp.y));
                    *(uint32_t*)&g_fxh[base + nf * 8 + q * 2] = *(uint32_t*)&hp;
                    *(uint32_t*)&g_fxl[base + nf * 8 + q * 2] = *(uint32_t*)&lp;
                }
            }
        }
}

// ---------------- K2: num = sw^T @ fx via tensor cores (ldmatrix.trans) ----------
__global__ __launch_bounds__(256) void k2() {
    extern __shared__ char sm[];
    const uint32_t sb = s2u(sm);
    const int bh = blockIdx.y, b = bh >> 3, h = bh & 7;
    const int n0 = blockIdx.x * 512;
    const int tid = threadIdx.x, lane = tid & 31, wid = tid >> 5;
    const int mt = wid & 3, np = wid >> 2;

    const int rr = tid >> 3, p8 = tid & 7;
    const int fr = (tid & 127) >> 2, fp = tid & 3;
    const int fsel = tid >> 7;
    const uint32_t d_swh = sb + rr * 144 + p8 * 16;
    const uint32_t d_swl = d_swh + 4608;
    const uint32_t d_fx = sb + 9216 + fsel * 2560 + fr * 80 + fp * 16;
    const __nv_bfloat16* s_swh = &g_swh[((size_t)(b * NN + n0 + rr)) * 512 + h * 64 + p8 * 8];
    const __nv_bfloat16* s_swl = &g_swl[((size_t)(b * NN + n0 + rr)) * 512 + h * 64 + p8 * 8];
    const __nv_bfloat16* s_fx =
        (fsel ? g_fxl : g_fxh) + ((size_t)(b * NN + n0 + fr)) * 256 + h * 32 + fp * 8;

    auto stg = [&](int s) {
        uint32_t so = (s & 3) * 14336;
        cpa16(d_swh + so, s_swh + (size_t)s * 32 * 512);
        cpa16(d_swl + so, s_swl + (size_t)s * 32 * 512);
        cpa16(d_fx + so, s_fx + (size_t)s * 32 * 256);
        cpa_commit();
    };

    const uint32_t a_off = (uint32_t)(((lane & 7) + ((lane >> 4) & 1) * 8) * 144 +
                                      (mt * 16 + ((lane >> 3) & 1) * 8) * 2);
    const uint32_t b_off = (uint32_t)(9216 + ((lane & 7) + ((lane >> 4) & 1) * 8) * 80 +
                                      (np * 16 + ((lane >> 3) & 1) * 8) * 2);
    const int dg = mt * 16 + (lane & 15);
    const int dr0 = (lane >> 4) * 16;

    float acc[2][4] = {{0.f, 0.f, 0.f, 0.f}, {0.f, 0.f, 0.f, 0.f}};
    float dden = 0.f;

    stg(0); stg(1); stg(2);
    #pragma unroll 1
    for (int c = 0; c < 16; ++c) {
        cpa_wait<2>();
        __syncthreads();
        if (c + 3 < 16) stg(c + 3); else cpa_commit();
        const uint32_t st = sb + (c & 3) * 14336;
        #pragma unroll
        for (int s16 = 0; s16 < 2; ++s16) {
            uint32_t ah[4], al[4], bhf[4], blf[4];
            ldsm4t(ah, st + a_off + s16 * 2304);
            ldsm4t(al, st + a_off + 4608 + s16 * 2304);
            ldsm4t(bhf, st + b_off + s16 * 1280);
            ldsm4t(blf, st + b_off + 2560 + s16 * 1280);
            #pragma unroll
            for (int nt = 0; nt < 2; ++nt) {
                mma_bf16(acc[nt], ah, bhf[nt], bhf[2 + nt]);
                mma_bf16(acc[nt], ah, blf[nt], blf[2 + nt]);
                mma_bf16(acc[nt], al, bhf[nt], bhf[2 + nt]);
            }
        }
        if (np == 0) {
            const char* sp = sm + (c & 3) * 14336;
            float ds = 0.f;
            #pragma unroll
            for (int r = 0; r < 16; ++r) {
                int row = dr0 + r;
                ds += __bfloat162float(*(const __nv_bfloat16*)(sp + row * 144 + dg * 2));
                ds += __bfloat162float(*(const __nv_bfloat16*)(sp + 4608 + row * 144 + dg * 2));
            }
            dden += ds;
        }
    }
    dden += __shfl_xor_sync(0xffffffffu, dden, 16);
    if (np == 0 && lane < 16) atomicAdd(&g_den[bh * 64 + dg], dden);
    #pragma unroll
    for (int nt = 0; nt < 2; ++nt)
        #pragma unroll
        for (int j = 0; j < 4; ++j) {
            int g = mt * 16 + (lane >> 2) + (j >> 1) * 8;
            int cc = np * 16 + nt * 8 + (lane & 3) * 2 + (j & 1);
            atomicAdd(&g_num[(bh * 64 + g) * 32 + cc], acc[nt][j]);
        }
}

// ---------------- K3: slice_att -> qkv -> SDPA -> fold Wout -> g_Mb -------------
__global__ __launch_bounds__(256) void k3(const float* __restrict__ Wqkv,
                                          const float* __restrict__ Wout) {
    __shared__ float S[11264];
    float* sa = S;
    float* wq = S + 2048;
    float* qs = S + 5120;
    float* ks2 = S + 7168;
    float* vs = S + 9216;
    float* sc = S;
    float* att = S + 5120;
    const int bh = blockIdx.x, b = bh >> 3, h = bh & 7;
    const int tid = threadIdx.x;
    for (int i = tid; i < 3072; i += 256) wq[i] = Wqkv[i];
    #pragma unroll
    for (int c = 0; c < 8; ++c) {
        int idx = tid * 8 + c;
        sa[idx] = g_num[bh * 2048 + idx] / (g_den[bh * 64 + (idx >> 5)] + 1e-5f);
    }
    __syncthreads();
    for (int t = tid; t < 6144; t += 256) {
        int g = t & 63, j = t >> 6;
        float s2 = 0.f;
        #pragma unroll
        for (int c = 0; c < 32; ++c) s2 += sa[g * 32 + c] * wq[j * 32 + c];
        if (j < 32) qs[g * 32 + j] = s2;
        else if (j < 64) ks2[g * 32 + (j - 32)] = s2;
        else vs[g * 32 + (j - 64)] = s2;
    }
    __syncthreads();
    for (int t = tid; t < 4096; t += 256) {
        int g = t >> 6, kk = t & 63;
        float s2 = 0.f;
        #pragma unroll
        for (int c = 0; c < 32; ++c) s2 += qs[g * 32 + c] * ks2[kk * 32 + c];
        sc[g * 65 + kk] = s2 * 0.17677669529663687f;
    }
    __syncthreads();
    if (tid < 64) {
        int g = tid;
        float m = -1e30f;
        #pragma unroll 8
        for (int kk = 0; kk < 64; ++kk) m = fmaxf(m, sc[g * 65 + kk]);
        float ssum = 0.f;
        #pragma unroll 8
        for (int kk = 0; kk < 64; ++kk) {
            float e = __expf(sc[g * 65 + kk] - m);
            sc[g * 65 + kk] = e;
            ssum += e;
        }
        float inv = 1.0f / ssum;
        #pragma unroll 8
        for (int kk = 0; kk < 64; ++kk) sc[g * 65 + kk] *= inv;
    }
    __syncthreads();
    for (int t = tid; t < 2048; t += 256) {
        int g = t >> 5, c = t & 31;
        float a = 0.f;
        #pragma unroll 8
        for (int kk = 0; kk < 64; ++kk) a += sc[g * 65 + kk] * vs[kk * 32 + c];
        att[g * 32 + c] = a;
    }
    __syncthreads();
    int d2 = tid;
    float wl[32];
    #pragma unroll
    for (int c = 0; c < 32; ++c) wl[c] = Wout[d2 * 256 + h * 32 + c];
    for (int g = 0; g < 64; ++g) {
        float s2 = 0.f;
        #pragma unroll
        for (int c = 0; c < 32; ++c) s2 += att[g * 32 + c] * wl[c];
        __nv_bfloat16 h16 = __float2bfloat16(s2);
        __nv_bfloat16 l16 = __float2bfloat16(s2 - __bfloat162float(h16));
        size_t o0 = (size_t)b * 256 * 1536 + (size_t)d2 * 1536 + h * 64 + g;
        g_Mb[o0] = h16;
        g_Mb[o0 + 512] = l16;
        g_Mb[o0 + 1024] = h16;
    }
}

// ---------------- K4: out = sw @ M + bout ([128x128] tile, K'=1536) --------------
__global__ __launch_bounds__(256, 2) void k4(float* __restrict__ out,
                                             const float* __restrict__ bout) {
    extern __shared__ char sm[];
    uint32_t sb = s2u(sm);
    const int tid = threadIdx.x, lane = tid & 31, wid = tid >> 5;
    const int wm = wid & 3, wn = wid >> 2;
    const int y = blockIdx.x;  // 0..1
    const int b = blockIdx.y >> 8, t0 = (blockIdx.y & 255) * 128;
    float* bias = (float*)(sm + 98304);
    if (tid < 128) bias[tid] = bout[y * 128 + tid];

    const __nv_bfloat16* swh = g_swh + (size_t)(b * NN + t0) * 512;
    const __nv_bfloat16* swl = g_swl + (size_t)(b * NN + t0) * 512;
    const __nv_bfloat16* Bsrc = g_Mb + (size_t)b * 256 * 1536 + (size_t)(y * 128) * 1536;

    float acc[2][8][4];
    #pragma unroll
    for (int i = 0; i < 2; ++i)
        #pragma unroll
        for (int j = 0; j < 8; ++j)
            #pragma unroll
            for (int k = 0; k < 4; ++k) acc[i][j][k] = 0.f;

    gemm128<24, 16, 8, 512, 1536>(swh, swl, Bsrc, sb, wm, wn, lane, acc);

    const int q = lane & 3, qr = lane >> 2;
    const int cbl = wn * 64;
    #pragma unroll
    for (int mf = 0; mf < 2; ++mf)
        #pragma unroll
        for (int half = 0; half < 2; ++half) {
            int rl = wm * 32 + mf * 16 + qr + half * 8;
            float* op = out + (size_t)(b * NN + t0 + rl) * 256 + y * 128 + cbl;
            #pragma unroll
            for (int nf = 0; nf < 8; ++nf) {
                float v0 = acc[mf][nf][half * 2 + 0] + bias[cbl + nf * 8 + q * 2 + 0];
                float v1 = acc[mf][nf][half * 2 + 1] + bias[cbl + nf * 8 + q * 2 + 1];
                *(float2*)(op + nf * 8 + q * 2) = make_float2(v0, v1);
            }
        }
}

extern "C" void kernel_launch(void* const* d_in, const int* in_sizes, int n_in,
                              void* d_out, int out_size) {
    const float* x = (const float*)d_in[0];
    const float* Wx = (const float*)d_in[1];
    const float* bx = (const float*)d_in[2];
    const float* Wfx = (const float*)d_in[3];
    const float* bfx = (const float*)d_in[4];
    const float* Wsl = (const float*)d_in[5];
    const float* bsl = (const float*)d_in[6];
    const float* temp = (const float*)d_in[7];
    const float* Wqkv = (const float*)d_in[8];
    const float* Wout = (const float*)d_in[9];
    const float* bout = (const float*)d_in[10];
    float* out = (float*)d_out;

    const int SMEM = 98304 + 512;  // 3 stages x 32KB + bias
    cudaFuncSetAttribute(k1, cudaFuncAttributeMaxDynamicSharedMemorySize, SMEM);
    cudaFuncSetAttribute(k4, cudaFuncAttributeMaxDynamicSharedMemorySize, SMEM);
    const int SMEM2 = 4 * 14336;  // 57344
    cudaFuncSetAttribute(k2, cudaFuncAttributeMaxDynamicSharedMemorySize, SMEM2);

    k0<<<768, 256>>>(Wx, bx, Wfx, bfx, Wsl, bsl, temp);
    kprep<<<16384, 256>>>(x);
    k1<<<dim3(6, 512), 256, SMEM>>>();
    k2<<<dim3(64, 16), 256, SMEM2>>>();
    k3<<<16, 256>>>(Wqkv, Wout);
    k4<<<dim3(2, 512), 256, SMEM>>>(out, bout);
}